// round 1
// baseline (speedup 1.0000x reference)
#include <cuda_runtime.h>
#include <cuda_fp8.h>
#include <math.h>

// Problem constants
#define NB 4
#define NT 2048
#define NC 1280
#define NH 10
#define ND 128
#define NF 5120
#define NBT (NB*NT)          // 8192
#define NC3 (3*NC)           // 3840
#define EPSF 1e-5f
#define ATT_SCALE 0.08838834764831845f   // 1/sqrt(128)

// ---------------------------------------------------------------------------
// Scratch (device globals — allocation-free per harness rules)
// ---------------------------------------------------------------------------
__device__ float g_xn  [(size_t)NBT * NC];        // rmsnorm output (reused twice)
__device__ float g_qkv [(size_t)NBT * NC3];       // qkv GEMM output
__device__ float g_q   [(size_t)NB * NH * NT * ND]; // (b,h,t,d) after rope/norm/qdq
__device__ float g_k   [(size_t)NB * NH * NT * ND];
__device__ float g_v   [(size_t)NB * NH * NT * ND];
__device__ float g_attn[(size_t)NBT * NC];        // attention out (b,t,c)
__device__ float g_y1  [(size_t)NBT * NC];        // post-attn residual stream
__device__ float g_h   [(size_t)NBT * NF];        // fc1+srelu output

// ---------------------------------------------------------------------------
// RMSNorm over rows: out = in * rsqrt(mean(in^2)+eps) * w
// One block (256 threads) per row.
// ---------------------------------------------------------------------------
__global__ __launch_bounds__(256)
void rmsnorm_rows(const float* __restrict__ in, const float* __restrict__ w,
                  float* __restrict__ out, int ncols) {
    int row = blockIdx.x;
    const float* p = in  + (size_t)row * ncols;
    float*       o = out + (size_t)row * ncols;
    float ss = 0.f;
    for (int c = threadIdx.x; c < ncols; c += 256) { float v = p[c]; ss = fmaf(v, v, ss); }
    #pragma unroll
    for (int off = 16; off; off >>= 1) ss += __shfl_xor_sync(0xffffffffu, ss, off);
    __shared__ float red[8];
    int wid = threadIdx.x >> 5, lane = threadIdx.x & 31;
    if (lane == 0) red[wid] = ss;
    __syncthreads();
    float tot = 0.f;
    #pragma unroll
    for (int i = 0; i < 8; i++) tot += red[i];
    float r = rsqrtf(tot / (float)ncols + EPSF);
    for (int c = threadIdx.x; c < ncols; c += 256) o[c] = p[c] * r * w[c];
}

// ---------------------------------------------------------------------------
// fp32 SGEMM, 128x128 tile, BK=16, 256 threads, 8x8 per thread.
// MODE 0: C = A*B      MODE 1: C = Res + A*B      MODE 2: C = srelu(A*B)
// Requires M%128==0, N%128==0, K%16==0 (all true here).
// A row-major [M,K], B row-major [K,N].
// ---------------------------------------------------------------------------
template <int MODE>
__global__ __launch_bounds__(256)
void sgemm128(const float* __restrict__ A, const float* __restrict__ B,
              const float* __restrict__ Res, float* __restrict__ Cout,
              int M, int N, int K) {
    __shared__ float As[16][132];   // stored transposed: As[k][m], padded
    __shared__ float Bs[16][128];   // Bs[k][n]

    const int bm = blockIdx.y << 7;
    const int bn = blockIdx.x << 7;
    const int tid = threadIdx.x;
    const int tx = tid & 15, ty = tid >> 4;

    float acc[8][8];
    #pragma unroll
    for (int i = 0; i < 8; i++)
        #pragma unroll
        for (int j = 0; j < 8; j++) acc[i][j] = 0.f;

    const int ar0 = tid >> 2;              // rows 0..63
    const int ar1 = ar0 + 64;              // rows 64..127
    const int ak  = (tid & 3) << 2;        // k sub 0,4,8,12
    const int bk0 = tid >> 5;              // 0..7
    const int bn0 = (tid & 31) << 2;       // 0..124

    const float* Ap = A + (size_t)bm * K;
    const float* Bp = B + bn;

    for (int k0 = 0; k0 < K; k0 += 16) {
        float4 a0 = *(const float4*)(Ap + (size_t)ar0 * K + k0 + ak);
        float4 a1 = *(const float4*)(Ap + (size_t)ar1 * K + k0 + ak);
        float4 b0 = *(const float4*)(Bp + (size_t)(k0 + bk0) * N + bn0);
        float4 b1 = *(const float4*)(Bp + (size_t)(k0 + bk0 + 8) * N + bn0);
        As[ak + 0][ar0] = a0.x; As[ak + 1][ar0] = a0.y;
        As[ak + 2][ar0] = a0.z; As[ak + 3][ar0] = a0.w;
        As[ak + 0][ar1] = a1.x; As[ak + 1][ar1] = a1.y;
        As[ak + 2][ar1] = a1.z; As[ak + 3][ar1] = a1.w;
        *(float4*)&Bs[bk0][bn0]     = b0;
        *(float4*)&Bs[bk0 + 8][bn0] = b1;
        __syncthreads();
        #pragma unroll
        for (int kk = 0; kk < 16; kk++) {
            float af[8], bf[8];
            #pragma unroll
            for (int i = 0; i < 8; i++) af[i] = As[kk][(ty << 3) + i];
            #pragma unroll
            for (int j = 0; j < 8; j++) bf[j] = Bs[kk][(tx << 3) + j];
            #pragma unroll
            for (int i = 0; i < 8; i++)
                #pragma unroll
                for (int j = 0; j < 8; j++)
                    acc[i][j] = fmaf(af[i], bf[j], acc[i][j]);
        }
        __syncthreads();
    }

    #pragma unroll
    for (int i = 0; i < 8; i++) {
        int row = bm + (ty << 3) + i;
        size_t base = (size_t)row * N + bn + (tx << 3);
        float vals[8];
        #pragma unroll
        for (int j = 0; j < 8; j++) {
            float v = acc[i][j];
            if (MODE == 1) v += Res[base + j];
            if (MODE == 2) { float t = fmaxf(v, 0.f); v = t * t; }
            vals[j] = v;
        }
        *(float4*)&Cout[base]     = make_float4(vals[0], vals[1], vals[2], vals[3]);
        *(float4*)&Cout[base + 4] = make_float4(vals[4], vals[5], vals[6], vals[7]);
    }
}

// ---------------------------------------------------------------------------
// MXFP8 quantize-dequantize for one element; 32-element block == one warp.
// Matches reference exactly: amax clip 1e-12, shared_exp = clip(floor(log2)+119,0,255),
// scale = 2^(127-se), clip ±448, e4m3 RN, deq by 2^(se-127).
// ---------------------------------------------------------------------------
__device__ __forceinline__ float qdq32(float x) {
    float a = fabsf(x);
    #pragma unroll
    for (int off = 16; off; off >>= 1) a = fmaxf(a, __shfl_xor_sync(0xffffffffu, a, off));
    a = fmaxf(a, 1e-12f);
    int se = ilogbf(a) + 119;          // floor(log2(amax)) + 127 - 8
    se = max(0, min(255, se));
    float scale = exp2f((float)(127 - se));
    float xs = fminf(fmaxf(x * scale, -448.f), 448.f);
    float xq = (float)__nv_fp8_e4m3(xs);   // round-to-nearest-even
    return xq * exp2f((float)(se - 127));
}

// ---------------------------------------------------------------------------
// QKV post-process: RoPE(q,k) -> per-head rmsnorm(q,k) -> qdq(q,k,v)
// One block (128 threads) per (b,t,h). Output layout (b,h,t,d) for attention.
// ---------------------------------------------------------------------------
__global__ __launch_bounds__(128)
void qkv_post(const float* __restrict__ qkv, const float* __restrict__ rope,
              const float* __restrict__ qn_w, const float* __restrict__ kn_w,
              float* __restrict__ gq, float* __restrict__ gk, float* __restrict__ gv) {
    int idx = blockIdx.x;
    int h  = idx % NH;
    int bt = idx / NH;
    int t  = bt % NT;
    int b  = bt / NT;
    int d  = threadIdx.x;

    const float* base = qkv + (size_t)bt * NC3 + h * ND;
    float qv = base[d];
    float kv = base[NC + d];
    float vv = base[2 * NC + d];

    // RoPE (rotate-half)
    float fr = rope[t * ND + d];
    float sn, cs;
    sincosf(fr, &sn, &cs);
    __shared__ float sq[ND], sk[ND];
    sq[d] = qv; sk[d] = kv;
    __syncthreads();
    float qr = (d < 64) ? -sq[d + 64] : sq[d - 64];
    float kr = (d < 64) ? -sk[d + 64] : sk[d - 64];
    qv = qv * cs + qr * sn;
    kv = kv * cs + kr * sn;

    // per-head rmsnorm over D=128 (4 warps)
    float s1 = qv * qv, s2 = kv * kv;
    #pragma unroll
    for (int off = 16; off; off >>= 1) {
        s1 += __shfl_xor_sync(0xffffffffu, s1, off);
        s2 += __shfl_xor_sync(0xffffffffu, s2, off);
    }
    __shared__ float r1[4], r2[4];
    int w = d >> 5, lane = d & 31;
    if (lane == 0) { r1[w] = s1; r2[w] = s2; }
    __syncthreads();
    float ssq = r1[0] + r1[1] + r1[2] + r1[3];
    float ssk = r2[0] + r2[1] + r2[2] + r2[3];
    qv *= rsqrtf(ssq * (1.f / ND) + EPSF) * qn_w[d];
    kv *= rsqrtf(ssk * (1.f / ND) + EPSF) * kn_w[d];

    // MXFP8 qdq (one 32-block per warp, d-contiguous — matches d//32 blocking)
    qv = qdq32(qv);
    kv = qdq32(kv);
    vv = qdq32(vv);

    size_t o = (((size_t)(b * NH + h)) * NT + t) * ND + d;
    gq[o] = qv; gk[o] = kv; gv[o] = vv;
}

// ---------------------------------------------------------------------------
// Causal flash attention, fp32. 64 q-rows x 64 k-cols tiles, D=128.
// grid = (T/64, B*H), 256 threads. Dynamic smem ~117KB.
// ---------------------------------------------------------------------------
#define AQ_PAD 129
#define AS_PAD 68

__global__ __launch_bounds__(256)
void attn_kernel(const float* __restrict__ gq, const float* __restrict__ gk,
                 const float* __restrict__ gv, float* __restrict__ gattn) {
    extern __shared__ float sm[];
    float* Qs   = sm;                      // 64*129
    float* Ks   = Qs + 64 * AQ_PAD;        // 64*129
    float* Vs   = Ks + 64 * AQ_PAD;        // 64*128
    float* Ss   = Vs + 64 * ND;            // 64*68
    float* rowm = Ss + 64 * AS_PAD;        // 64
    float* rowl = rowm + 64;               // 64
    float* alph = rowl + 64;               // 64

    const int tid  = threadIdx.x;
    const int qblk = blockIdx.x;
    const int q0   = qblk << 6;
    const int bh   = blockIdx.y;
    const int b    = bh / NH, h = bh % NH;

    // Load Q tile once
    const float* qbase = gq + ((size_t)bh * NT + q0) * ND;
    #pragma unroll
    for (int l = 0; l < 8; l++) {
        int j = tid + l * 256;
        int r = j >> 5, c = (j & 31) << 2;
        float4 v = *(const float4*)(qbase + r * ND + c);
        Qs[r * AQ_PAD + c]     = v.x; Qs[r * AQ_PAD + c + 1] = v.y;
        Qs[r * AQ_PAD + c + 2] = v.z; Qs[r * AQ_PAD + c + 3] = v.w;
    }
    if (tid < 64) { rowm[tid] = -INFINITY; rowl[tid] = 0.f; }

    float Oacc[4][8];
    #pragma unroll
    for (int i = 0; i < 4; i++)
        #pragma unroll
        for (int j = 0; j < 8; j++) Oacc[i][j] = 0.f;

    const int scr  = (tid >> 4) << 2;   // S row base (4 rows)
    const int scc  = (tid & 15) << 2;   // S col base (4 cols)
    const int sr   = tid >> 2;          // softmax row
    const int sl   = tid & 3;           // softmax lane within row-quad
    const int orow = (tid >> 4) << 2;   // O row base (4 rows)
    const int ocol = (tid & 15) << 3;   // O col base (8 cols)

    const int nkt = qblk + 1;
    for (int kt = 0; kt < nkt; kt++) {
        __syncthreads();   // protect Ks/Vs/Ss from previous iteration
        const float* kbase = gk + ((size_t)bh * NT + (kt << 6)) * ND;
        const float* vbase = gv + ((size_t)bh * NT + (kt << 6)) * ND;
        #pragma unroll
        for (int l = 0; l < 8; l++) {
            int j = tid + l * 256;
            int r = j >> 5, c = (j & 31) << 2;
            float4 k4 = *(const float4*)(kbase + r * ND + c);
            Ks[r * AQ_PAD + c]     = k4.x; Ks[r * AQ_PAD + c + 1] = k4.y;
            Ks[r * AQ_PAD + c + 2] = k4.z; Ks[r * AQ_PAD + c + 3] = k4.w;
            float4 v4 = *(const float4*)(vbase + r * ND + c);
            *(float4*)&Vs[r * ND + c] = v4;
        }
        __syncthreads();

        // S = Q K^T  (4x4 per thread)
        float sacc[4][4];
        #pragma unroll
        for (int i = 0; i < 4; i++)
            #pragma unroll
            for (int j = 0; j < 4; j++) sacc[i][j] = 0.f;
        for (int kk = 0; kk < ND; kk++) {
            float qf[4], kf[4];
            #pragma unroll
            for (int i = 0; i < 4; i++) qf[i] = Qs[(scr + i) * AQ_PAD + kk];
            #pragma unroll
            for (int j = 0; j < 4; j++) kf[j] = Ks[(scc + j) * AQ_PAD + kk];
            #pragma unroll
            for (int i = 0; i < 4; i++)
                #pragma unroll
                for (int j = 0; j < 4; j++)
                    sacc[i][j] = fmaf(qf[i], kf[j], sacc[i][j]);
        }
        #pragma unroll
        for (int i = 0; i < 4; i++)
            #pragma unroll
            for (int j = 0; j < 4; j++)
                Ss[(scr + i) * AS_PAD + scc + j] = sacc[i][j];
        __syncthreads();

        // Online softmax (4 threads per row)
        int kmax = q0 + sr - (kt << 6);   // valid col j <= kmax
        float sv[16];
        float mloc = -INFINITY;
        #pragma unroll
        for (int i = 0; i < 16; i++) {
            int j = sl + (i << 2);
            float s = (j <= kmax) ? Ss[sr * AS_PAD + j] * ATT_SCALE : -INFINITY;
            sv[i] = s;
            mloc = fmaxf(mloc, s);
        }
        mloc = fmaxf(mloc, __shfl_xor_sync(0xffffffffu, mloc, 1));
        mloc = fmaxf(mloc, __shfl_xor_sync(0xffffffffu, mloc, 2));
        float mprev = rowm[sr];
        float mnew  = fmaxf(mprev, mloc);
        float ls = 0.f;
        #pragma unroll
        for (int i = 0; i < 16; i++) {
            float p = __expf(sv[i] - mnew);   // -inf -> 0
            Ss[sr * AS_PAD + sl + (i << 2)] = p;
            ls += p;
        }
        ls += __shfl_xor_sync(0xffffffffu, ls, 1);
        ls += __shfl_xor_sync(0xffffffffu, ls, 2);
        if (sl == 0) {
            float a = __expf(mprev - mnew);
            alph[sr] = a;
            rowl[sr] = rowl[sr] * a + ls;
            rowm[sr] = mnew;
        }
        __syncthreads();

        // O = O*alpha + P@V   (4 rows x 8 cols per thread)
        float av[4];
        #pragma unroll
        for (int i = 0; i < 4; i++) av[i] = alph[orow + i];
        #pragma unroll
        for (int i = 0; i < 4; i++)
            #pragma unroll
            for (int j = 0; j < 8; j++) Oacc[i][j] *= av[i];
        for (int j2 = 0; j2 < 64; j2++) {
            float pf[4];
            #pragma unroll
            for (int i = 0; i < 4; i++) pf[i] = Ss[(orow + i) * AS_PAD + j2];
            float4 v0 = *(float4*)&Vs[j2 * ND + ocol];
            float4 v1 = *(float4*)&Vs[j2 * ND + ocol + 4];
            #pragma unroll
            for (int i = 0; i < 4; i++) {
                Oacc[i][0] = fmaf(pf[i], v0.x, Oacc[i][0]);
                Oacc[i][1] = fmaf(pf[i], v0.y, Oacc[i][1]);
                Oacc[i][2] = fmaf(pf[i], v0.z, Oacc[i][2]);
                Oacc[i][3] = fmaf(pf[i], v0.w, Oacc[i][3]);
                Oacc[i][4] = fmaf(pf[i], v1.x, Oacc[i][4]);
                Oacc[i][5] = fmaf(pf[i], v1.y, Oacc[i][5]);
                Oacc[i][6] = fmaf(pf[i], v1.z, Oacc[i][6]);
                Oacc[i][7] = fmaf(pf[i], v1.w, Oacc[i][7]);
            }
        }
    }

    // Normalize and write out (b,t,h*128+c)
    #pragma unroll
    for (int i = 0; i < 4; i++) {
        float linv = 1.f / rowl[orow + i];
        size_t off = ((size_t)b * NT + q0 + orow + i) * NC + h * ND + ocol;
        *(float4*)&gattn[off] = make_float4(Oacc[i][0] * linv, Oacc[i][1] * linv,
                                            Oacc[i][2] * linv, Oacc[i][3] * linv);
        *(float4*)&gattn[off + 4] = make_float4(Oacc[i][4] * linv, Oacc[i][5] * linv,
                                                Oacc[i][6] * linv, Oacc[i][7] * linv);
    }
}

// ---------------------------------------------------------------------------
// Launch
// ---------------------------------------------------------------------------
static const int ATT_SMEM = (64 * AQ_PAD * 2 + 64 * ND + 64 * AS_PAD + 192) * (int)sizeof(float);

extern "C" void kernel_launch(void* const* d_in, const int* in_sizes, int n_in,
                              void* d_out, int out_size) {
    const float* x      = (const float*)d_in[0];
    const float* rope   = (const float*)d_in[1];
    const float* ln1_w  = (const float*)d_in[2];
    const float* w_qkv  = (const float*)d_in[3];
    const float* qn_w   = (const float*)d_in[4];
    const float* kn_w   = (const float*)d_in[5];
    const float* w_out  = (const float*)d_in[6];
    const float* ln2_w  = (const float*)d_in[7];
    const float* w_fc1  = (const float*)d_in[8];
    const float* w_fc2  = (const float*)d_in[9];
    float* out = (float*)d_out;

    float *xn, *qkv, *q, *k, *v, *attn, *y1, *hb;
    cudaGetSymbolAddress((void**)&xn,   g_xn);
    cudaGetSymbolAddress((void**)&qkv,  g_qkv);
    cudaGetSymbolAddress((void**)&q,    g_q);
    cudaGetSymbolAddress((void**)&k,    g_k);
    cudaGetSymbolAddress((void**)&v,    g_v);
    cudaGetSymbolAddress((void**)&attn, g_attn);
    cudaGetSymbolAddress((void**)&y1,   g_y1);
    cudaGetSymbolAddress((void**)&hb,   g_h);

    cudaFuncSetAttribute(attn_kernel, cudaFuncAttributeMaxDynamicSharedMemorySize, ATT_SMEM);

    // 1) rmsnorm(x, ln1_w)
    rmsnorm_rows<<<NBT, 256>>>(x, ln1_w, xn, NC);

    // 2) qkv = xn @ w_qkv   [8192,1280]x[1280,3840]
    sgemm128<0><<<dim3(NC3 / 128, NBT / 128), 256>>>(xn, w_qkv, nullptr, qkv, NBT, NC3, NC);

    // 3) RoPE + head rmsnorm + mxfp8 qdq  -> (b,h,t,d)
    qkv_post<<<NB * NT * NH, 128>>>(qkv, rope, qn_w, kn_w, q, k, v);

    // 4) causal attention
    attn_kernel<<<dim3(NT / 64, NB * NH), 256, ATT_SMEM>>>(q, k, v, attn);

    // 5) y1 = x + attn @ w_out
    sgemm128<1><<<dim3(NC / 128, NBT / 128), 256>>>(attn, w_out, x, y1, NBT, NC, NC);

    // 6) rmsnorm(y1, ln2_w)
    rmsnorm_rows<<<NBT, 256>>>(y1, ln2_w, xn, NC);

    // 7) h = srelu(xn @ w_fc1)   [8192,1280]x[1280,5120]
    sgemm128<2><<<dim3(NF / 128, NBT / 128), 256>>>(xn, w_fc1, nullptr, hb, NBT, NF, NC);

    // 8) out = y1 + h @ w_fc2    [8192,5120]x[5120,1280]
    sgemm128<1><<<dim3(NC / 128, NBT / 128), 256>>>(hb, w_fc2, y1, out, NBT, NC, NF);
}

// round 3
// speedup vs baseline: 2.1751x; 2.1751x over previous
#include <cuda_runtime.h>
#include <cuda_bf16.h>
#include <cuda_fp8.h>
#include <math.h>
#include <stdint.h>

// Problem constants
#define NB 4
#define NT 2048
#define NC 1280
#define NH 10
#define ND 128
#define NF 5120
#define NBT (NB*NT)          // 8192
#define NC3 (3*NC)           // 3840
#define EPSF 1e-5f
#define ATT_SCALE 0.08838834764831845f   // 1/sqrt(128)

// ---------------------------------------------------------------------------
// Scratch (device globals — allocation-free per harness rules)
// ---------------------------------------------------------------------------
__device__ __nv_bfloat16 g_xn_hi[(size_t)NBT * NC];
__device__ __nv_bfloat16 g_xn_lo[(size_t)NBT * NC];
__device__ float g_qkv[(size_t)NBT * NC3];
__device__ float g_q  [(size_t)NB * NH * NT * ND];
__device__ float g_k  [(size_t)NB * NH * NT * ND];
__device__ float g_v  [(size_t)NB * NH * NT * ND];
__device__ __nv_bfloat16 g_at_hi[(size_t)NBT * NC];
__device__ __nv_bfloat16 g_at_lo[(size_t)NBT * NC];
__device__ float g_y1 [(size_t)NBT * NC];
__device__ __nv_bfloat16 g_h_hi[(size_t)NBT * NF];
__device__ __nv_bfloat16 g_h_lo[(size_t)NBT * NF];
// transposed+split weights [N,K]
__device__ __nv_bfloat16 g_wqkvT_h[(size_t)NC3 * NC];
__device__ __nv_bfloat16 g_wqkvT_l[(size_t)NC3 * NC];
__device__ __nv_bfloat16 g_woutT_h[(size_t)NC * NC];
__device__ __nv_bfloat16 g_woutT_l[(size_t)NC * NC];
__device__ __nv_bfloat16 g_wfc1T_h[(size_t)NF * NC];
__device__ __nv_bfloat16 g_wfc1T_l[(size_t)NF * NC];
__device__ __nv_bfloat16 g_wfc2T_h[(size_t)NC * NF];
__device__ __nv_bfloat16 g_wfc2T_l[(size_t)NC * NF];

// ---------------------------------------------------------------------------
// PTX helpers (baseline ISA only: cp.async / ldmatrix / mma.sync)
// ---------------------------------------------------------------------------
__device__ __forceinline__ uint32_t smem_u32(const void* p) {
    uint32_t a;
    asm("{ .reg .u64 t; cvta.to.shared.u64 t, %1; cvt.u32.u64 %0, t; }" : "=r"(a) : "l"(p));
    return a;
}
__device__ __forceinline__ void cp16(uint32_t dst, const void* src) {
    asm volatile("cp.async.cg.shared.global [%0], [%1], 16;" :: "r"(dst), "l"(src));
}
__device__ __forceinline__ void ldsm_x4(uint32_t& r0, uint32_t& r1, uint32_t& r2,
                                        uint32_t& r3, uint32_t addr) {
    asm volatile("ldmatrix.sync.aligned.m8n8.x4.shared.b16 {%0,%1,%2,%3}, [%4];"
                 : "=r"(r0), "=r"(r1), "=r"(r2), "=r"(r3) : "r"(addr));
}
__device__ __forceinline__ void mma16816(float* c, const uint32_t* a,
                                         uint32_t b0, uint32_t b1) {
    asm volatile(
        "mma.sync.aligned.m16n8k16.row.col.f32.bf16.bf16.f32 "
        "{%0,%1,%2,%3}, {%4,%5,%6,%7}, {%8,%9}, {%0,%1,%2,%3};"
        : "+f"(c[0]), "+f"(c[1]), "+f"(c[2]), "+f"(c[3])
        : "r"(a[0]), "r"(a[1]), "r"(a[2]), "r"(a[3]), "r"(b0), "r"(b1));
}

// ---------------------------------------------------------------------------
// hi/lo bf16 split
// ---------------------------------------------------------------------------
__device__ __forceinline__ void split_bf16(float v, __nv_bfloat16& h, __nv_bfloat16& l) {
    h = __float2bfloat16(v);
    l = __float2bfloat16(v - __bfloat162float(h));
}

// ---------------------------------------------------------------------------
// RMSNorm -> hi/lo bf16 split. One block (256 threads) per row.
// ---------------------------------------------------------------------------
__global__ __launch_bounds__(256)
void rmsnorm_split(const float* __restrict__ in, const float* __restrict__ w,
                   __nv_bfloat16* __restrict__ ohi, __nv_bfloat16* __restrict__ olo,
                   int ncols) {
    int row = blockIdx.x;
    const float* p = in + (size_t)row * ncols;
    size_t ob = (size_t)row * ncols;
    float ss = 0.f;
    for (int c = threadIdx.x; c < ncols; c += 256) { float v = p[c]; ss = fmaf(v, v, ss); }
    #pragma unroll
    for (int off = 16; off; off >>= 1) ss += __shfl_xor_sync(0xffffffffu, ss, off);
    __shared__ float red[8];
    int wid = threadIdx.x >> 5, lane = threadIdx.x & 31;
    if (lane == 0) red[wid] = ss;
    __syncthreads();
    float tot = 0.f;
    #pragma unroll
    for (int i = 0; i < 8; i++) tot += red[i];
    float r = rsqrtf(tot / (float)ncols + EPSF);
    for (int c = threadIdx.x; c < ncols; c += 256) {
        float v = p[c] * r * w[c];
        __nv_bfloat16 h, l; split_bf16(v, h, l);
        ohi[ob + c] = h; olo[ob + c] = l;
    }
}

// ---------------------------------------------------------------------------
// Weight transpose + split: W [K,N] fp32 -> Thi/Tlo [N,K] bf16
// ---------------------------------------------------------------------------
__global__ __launch_bounds__(256)
void wsplit(const float* __restrict__ W, __nv_bfloat16* __restrict__ Thi,
            __nv_bfloat16* __restrict__ Tlo, int K, int N) {
    __shared__ float t[32][33];
    int n0 = blockIdx.x * 32, k0 = blockIdx.y * 32;
    int tx = threadIdx.x & 31, ty = threadIdx.x >> 5;
    #pragma unroll
    for (int i = 0; i < 4; i++) {
        int k = ty + i * 8;
        t[k][tx] = W[(size_t)(k0 + k) * N + n0 + tx];
    }
    __syncthreads();
    #pragma unroll
    for (int i = 0; i < 4; i++) {
        int n = ty + i * 8;
        float v = t[tx][n];
        __nv_bfloat16 h, l; split_bf16(v, h, l);
        Thi[(size_t)(n0 + n) * K + k0 + tx] = h;
        Tlo[(size_t)(n0 + n) * K + k0 + tx] = l;
    }
}

// ---------------------------------------------------------------------------
// mma.sync bf16 GEMM with 3-term hi/lo split:
//   C[M,N] = Ahi*Bhi^T + Ahi*Blo^T + Alo*Bhi^T  (A [M,K], B [N,K] row-major)
// CTA tile 128x128, BK=32, 8 warps (warp tile 32x64), double-buffered cp.async.
// MODE 0: Cf = C   MODE 1: Cf = Res + C   MODE 2: Chi/Clo = split(srelu(C))
// ---------------------------------------------------------------------------
#define APAD 40                       // bf16 elems per smem row (32 + 8 pad)
#define TILE_B (128 * APAD * 2)       // 10240 bytes per tile
#define STAGE_B (4 * TILE_B)          // Ah, Al, Bh, Bl

__device__ __forceinline__ void gemm_load_stage(
    uint32_t st, const char* Ah, const char* Al, const char* Bh, const char* Bl,
    size_t rowb, size_t ko, int tid) {
    #pragma unroll
    for (int i = 0; i < 2; i++) {
        int idx = tid + i * 256;
        int r = idx >> 2, c = idx & 3;
        uint32_t dst = st + (uint32_t)(r * 80 + c * 16);
        size_t src = (size_t)r * rowb + ko + (size_t)c * 16;
        cp16(dst + 0u * TILE_B, Ah + src);
        cp16(dst + 1u * TILE_B, Al + src);
        cp16(dst + 2u * TILE_B, Bh + src);
        cp16(dst + 3u * TILE_B, Bl + src);
    }
    asm volatile("cp.async.commit_group;" ::: "memory");
}

template <int MODE>
__global__ __launch_bounds__(256)
void gemm_mma(const __nv_bfloat16* __restrict__ Ahi, const __nv_bfloat16* __restrict__ Alo,
              const __nv_bfloat16* __restrict__ Bhi, const __nv_bfloat16* __restrict__ Blo,
              const float* __restrict__ Res, float* __restrict__ Cf,
              __nv_bfloat16* __restrict__ Chi, __nv_bfloat16* __restrict__ Clo,
              int M, int N, int K) {
    extern __shared__ char smem[];
    const uint32_t sb = smem_u32(smem);
    const int tid  = threadIdx.x;
    const int warp = tid >> 5, lane = tid & 31;
    const int warp_m = warp & 3;          // 4 warps over M (32 rows each)
    const int warp_n = warp >> 2;         // 2 warps over N (64 cols each)
    const int bm = blockIdx.y << 7;
    const int bn = blockIdx.x << 7;

    float acc[2][8][4];
    #pragma unroll
    for (int i = 0; i < 2; i++)
        #pragma unroll
        for (int j = 0; j < 8; j++)
            #pragma unroll
            for (int q = 0; q < 4; q++) acc[i][j][q] = 0.f;

    const size_t rowb = (size_t)K * 2;
    const char* Ah0 = (const char*)Ahi + (size_t)bm * rowb;
    const char* Al0 = (const char*)Alo + (size_t)bm * rowb;
    const char* Bh0 = (const char*)Bhi + (size_t)bn * rowb;
    const char* Bl0 = (const char*)Blo + (size_t)bn * rowb;

    const int NIT = K >> 5;   // BK = 32

    gemm_load_stage(sb, Ah0, Al0, Bh0, Bl0, rowb, 0, tid);

    // per-lane ldmatrix offsets (within tile, bytes)
    const int arow = warp_m * 32 + (lane & 15);
    const int acolb = ((lane >> 4) << 3);         // +0 or +8 elems
    const int brow = warp_n * 64 + (lane & 7) + ((lane >> 4) << 3);
    const int bcolb = (lane & 8);                 // +0 or +8 elems

    for (int it = 0; it < NIT; it++) {
        if (it + 1 < NIT)
            gemm_load_stage(sb + (uint32_t)(((it + 1) & 1) * STAGE_B),
                            Ah0, Al0, Bh0, Bl0, rowb, (size_t)(it + 1) * 64, tid);
        if (it + 1 < NIT)
            asm volatile("cp.async.wait_group 1;" ::: "memory");
        else
            asm volatile("cp.async.wait_group 0;" ::: "memory");
        __syncthreads();

        const uint32_t st  = sb + (uint32_t)((it & 1) * STAGE_B);
        const uint32_t sah = st;
        const uint32_t sal = st + TILE_B;
        const uint32_t sbh = st + 2u * TILE_B;
        const uint32_t sbl = st + 3u * TILE_B;

        #pragma unroll
        for (int ks = 0; ks < 2; ks++) {
            uint32_t ah[2][4], al[2][4], bh[4][4], bl[4][4];
            const int acol = ks * 16 + acolb;
            const int bcol = ks * 16 + bcolb;
            #pragma unroll
            for (int mi = 0; mi < 2; mi++) {
                uint32_t off = (uint32_t)(((arow + mi * 16) * APAD + acol) * 2);
                ldsm_x4(ah[mi][0], ah[mi][1], ah[mi][2], ah[mi][3], sah + off);
                ldsm_x4(al[mi][0], al[mi][1], al[mi][2], al[mi][3], sal + off);
            }
            #pragma unroll
            for (int ni = 0; ni < 4; ni++) {
                uint32_t off = (uint32_t)(((brow + ni * 16) * APAD + bcol) * 2);
                ldsm_x4(bh[ni][0], bh[ni][1], bh[ni][2], bh[ni][3], sbh + off);
                ldsm_x4(bl[ni][0], bl[ni][1], bl[ni][2], bl[ni][3], sbl + off);
            }
            #pragma unroll
            for (int mi = 0; mi < 2; mi++) {
                #pragma unroll
                for (int ni = 0; ni < 4; ni++) {
                    mma16816(acc[mi][2 * ni],     ah[mi], bh[ni][0], bh[ni][1]);
                    mma16816(acc[mi][2 * ni + 1], ah[mi], bh[ni][2], bh[ni][3]);
                    mma16816(acc[mi][2 * ni],     ah[mi], bl[ni][0], bl[ni][1]);
                    mma16816(acc[mi][2 * ni + 1], ah[mi], bl[ni][2], bl[ni][3]);
                    mma16816(acc[mi][2 * ni],     al[mi], bh[ni][0], bh[ni][1]);
                    mma16816(acc[mi][2 * ni + 1], al[mi], bh[ni][2], bh[ni][3]);
                }
            }
        }
        __syncthreads();
    }

    // Epilogue: each thread owns pairs (row, col..col+1) per (mi, nj, half)
    const int r0 = bm + warp_m * 32 + (lane >> 2);
    const int c0 = bn + warp_n * 64 + 2 * (lane & 3);
    #pragma unroll
    for (int mi = 0; mi < 2; mi++) {
        #pragma unroll
        for (int half = 0; half < 2; half++) {
            int row = r0 + mi * 16 + half * 8;
            size_t rb = (size_t)row * N;
            #pragma unroll
            for (int nj = 0; nj < 8; nj++) {
                int col = c0 + nj * 8;
                float v0 = acc[mi][nj][2 * half];
                float v1 = acc[mi][nj][2 * half + 1];
                size_t o = rb + col;
                if (MODE == 0) {
                    *(float2*)&Cf[o] = make_float2(v0, v1);
                } else if (MODE == 1) {
                    float2 rv = *(const float2*)&Res[o];
                    *(float2*)&Cf[o] = make_float2(v0 + rv.x, v1 + rv.y);
                } else {
                    float t0 = fmaxf(v0, 0.f); v0 = t0 * t0;
                    float t1 = fmaxf(v1, 0.f); v1 = t1 * t1;
                    __nv_bfloat16 h0, l0, h1, l1;
                    split_bf16(v0, h0, l0); split_bf16(v1, h1, l1);
                    *(__nv_bfloat162*)&Chi[o] = __nv_bfloat162(h0, h1);
                    *(__nv_bfloat162*)&Clo[o] = __nv_bfloat162(l0, l1);
                }
            }
        }
    }
}

// ---------------------------------------------------------------------------
// MXFP8 qdq (32-element block == one warp)
// ---------------------------------------------------------------------------
__device__ __forceinline__ float qdq32(float x) {
    float a = fabsf(x);
    #pragma unroll
    for (int off = 16; off; off >>= 1) a = fmaxf(a, __shfl_xor_sync(0xffffffffu, a, off));
    a = fmaxf(a, 1e-12f);
    int se = ilogbf(a) + 119;
    se = max(0, min(255, se));
    float scale = exp2f((float)(127 - se));
    float xs = fminf(fmaxf(x * scale, -448.f), 448.f);
    float xq = (float)__nv_fp8_e4m3(xs);
    return xq * exp2f((float)(se - 127));
}

// ---------------------------------------------------------------------------
// QKV post-process: RoPE -> head rmsnorm -> qdq -> (b,h,t,d) fp32
// ---------------------------------------------------------------------------
__global__ __launch_bounds__(128)
void qkv_post(const float* __restrict__ qkv, const float* __restrict__ rope,
              const float* __restrict__ qn_w, const float* __restrict__ kn_w,
              float* __restrict__ gq, float* __restrict__ gk, float* __restrict__ gv) {
    int idx = blockIdx.x;
    int h  = idx % NH;
    int bt = idx / NH;
    int t  = bt % NT;
    int b  = bt / NT;
    int d  = threadIdx.x;

    const float* base = qkv + (size_t)bt * NC3 + h * ND;
    float qv = base[d];
    float kv = base[NC + d];
    float vv = base[2 * NC + d];

    float fr = rope[t * ND + d];
    float sn, cs;
    sincosf(fr, &sn, &cs);
    __shared__ float sq[ND], sk[ND];
    sq[d] = qv; sk[d] = kv;
    __syncthreads();
    float qr = (d < 64) ? -sq[d + 64] : sq[d - 64];
    float kr = (d < 64) ? -sk[d + 64] : sk[d - 64];
    qv = qv * cs + qr * sn;
    kv = kv * cs + kr * sn;

    float s1 = qv * qv, s2 = kv * kv;
    #pragma unroll
    for (int off = 16; off; off >>= 1) {
        s1 += __shfl_xor_sync(0xffffffffu, s1, off);
        s2 += __shfl_xor_sync(0xffffffffu, s2, off);
    }
    __shared__ float r1[4], r2[4];
    int w = d >> 5, lane = d & 31;
    if (lane == 0) { r1[w] = s1; r2[w] = s2; }
    __syncthreads();
    float ssq = r1[0] + r1[1] + r1[2] + r1[3];
    float ssk = r2[0] + r2[1] + r2[2] + r2[3];
    qv *= rsqrtf(ssq * (1.f / ND) + EPSF) * qn_w[d];
    kv *= rsqrtf(ssk * (1.f / ND) + EPSF) * kn_w[d];

    qv = qdq32(qv);
    kv = qdq32(kv);
    vv = qdq32(vv);

    size_t o = (((size_t)(b * NH + h)) * NT + t) * ND + d;
    gq[o] = qv; gk[o] = kv; gv[o] = vv;
}

// ---------------------------------------------------------------------------
// Causal flash attention, fp32. 64x64 tiles, D=128. Epilogue writes hi/lo bf16.
// ---------------------------------------------------------------------------
#define AQ_PAD 129
#define AS_PAD 68

__global__ __launch_bounds__(256)
void attn_kernel(const float* __restrict__ gq, const float* __restrict__ gk,
                 const float* __restrict__ gv,
                 __nv_bfloat16* __restrict__ ahi, __nv_bfloat16* __restrict__ alo) {
    extern __shared__ float sm[];
    float* Qs   = sm;
    float* Ks   = Qs + 64 * AQ_PAD;
    float* Vs   = Ks + 64 * AQ_PAD;
    float* Ss   = Vs + 64 * ND;
    float* rowm = Ss + 64 * AS_PAD;
    float* rowl = rowm + 64;
    float* alph = rowl + 64;

    const int tid  = threadIdx.x;
    const int qblk = blockIdx.x;
    const int q0   = qblk << 6;
    const int bh   = blockIdx.y;
    const int b    = bh / NH, h = bh % NH;

    const float* qbase = gq + ((size_t)bh * NT + q0) * ND;
    #pragma unroll
    for (int l = 0; l < 8; l++) {
        int j = tid + l * 256;
        int r = j >> 5, c = (j & 31) << 2;
        float4 v = *(const float4*)(qbase + r * ND + c);
        Qs[r * AQ_PAD + c]     = v.x; Qs[r * AQ_PAD + c + 1] = v.y;
        Qs[r * AQ_PAD + c + 2] = v.z; Qs[r * AQ_PAD + c + 3] = v.w;
    }
    if (tid < 64) { rowm[tid] = -INFINITY; rowl[tid] = 0.f; }

    float Oacc[4][8];
    #pragma unroll
    for (int i = 0; i < 4; i++)
        #pragma unroll
        for (int j = 0; j < 8; j++) Oacc[i][j] = 0.f;

    const int scr  = (tid >> 4) << 2;
    const int scc  = (tid & 15) << 2;
    const int sr   = tid >> 2;
    const int sl   = tid & 3;
    const int orow = (tid >> 4) << 2;
    const int ocol = (tid & 15) << 3;

    const int nkt = qblk + 1;
    for (int kt = 0; kt < nkt; kt++) {
        __syncthreads();
        const float* kbase = gk + ((size_t)bh * NT + (kt << 6)) * ND;
        const float* vbase = gv + ((size_t)bh * NT + (kt << 6)) * ND;
        #pragma unroll
        for (int l = 0; l < 8; l++) {
            int j = tid + l * 256;
            int r = j >> 5, c = (j & 31) << 2;
            float4 k4 = *(const float4*)(kbase + r * ND + c);
            Ks[r * AQ_PAD + c]     = k4.x; Ks[r * AQ_PAD + c + 1] = k4.y;
            Ks[r * AQ_PAD + c + 2] = k4.z; Ks[r * AQ_PAD + c + 3] = k4.w;
            float4 v4 = *(const float4*)(vbase + r * ND + c);
            *(float4*)&Vs[r * ND + c] = v4;
        }
        __syncthreads();

        float sacc[4][4];
        #pragma unroll
        for (int i = 0; i < 4; i++)
            #pragma unroll
            for (int j = 0; j < 4; j++) sacc[i][j] = 0.f;
        for (int kk = 0; kk < ND; kk++) {
            float qf[4], kf[4];
            #pragma unroll
            for (int i = 0; i < 4; i++) qf[i] = Qs[(scr + i) * AQ_PAD + kk];
            #pragma unroll
            for (int j = 0; j < 4; j++) kf[j] = Ks[(scc + j) * AQ_PAD + kk];
            #pragma unroll
            for (int i = 0; i < 4; i++)
                #pragma unroll
                for (int j = 0; j < 4; j++)
                    sacc[i][j] = fmaf(qf[i], kf[j], sacc[i][j]);
        }
        #pragma unroll
        for (int i = 0; i < 4; i++)
            #pragma unroll
            for (int j = 0; j < 4; j++)
                Ss[(scr + i) * AS_PAD + scc + j] = sacc[i][j];
        __syncthreads();

        int kmax = q0 + sr - (kt << 6);
        float sv[16];
        float mloc = -INFINITY;
        #pragma unroll
        for (int i = 0; i < 16; i++) {
            int j = sl + (i << 2);
            float s = (j <= kmax) ? Ss[sr * AS_PAD + j] * ATT_SCALE : -INFINITY;
            sv[i] = s;
            mloc = fmaxf(mloc, s);
        }
        mloc = fmaxf(mloc, __shfl_xor_sync(0xffffffffu, mloc, 1));
        mloc = fmaxf(mloc, __shfl_xor_sync(0xffffffffu, mloc, 2));
        float mprev = rowm[sr];
        float mnew  = fmaxf(mprev, mloc);
        float ls = 0.f;
        #pragma unroll
        for (int i = 0; i < 16; i++) {
            float p = __expf(sv[i] - mnew);
            Ss[sr * AS_PAD + sl + (i << 2)] = p;
            ls += p;
        }
        ls += __shfl_xor_sync(0xffffffffu, ls, 1);
        ls += __shfl_xor_sync(0xffffffffu, ls, 2);
        if (sl == 0) {
            float a = __expf(mprev - mnew);
            alph[sr] = a;
            rowl[sr] = rowl[sr] * a + ls;
            rowm[sr] = mnew;
        }
        __syncthreads();

        float av[4];
        #pragma unroll
        for (int i = 0; i < 4; i++) av[i] = alph[orow + i];
        #pragma unroll
        for (int i = 0; i < 4; i++)
            #pragma unroll
            for (int j = 0; j < 8; j++) Oacc[i][j] *= av[i];
        for (int j2 = 0; j2 < 64; j2++) {
            float pf[4];
            #pragma unroll
            for (int i = 0; i < 4; i++) pf[i] = Ss[(orow + i) * AS_PAD + j2];
            float4 v0 = *(float4*)&Vs[j2 * ND + ocol];
            float4 v1 = *(float4*)&Vs[j2 * ND + ocol + 4];
            #pragma unroll
            for (int i = 0; i < 4; i++) {
                Oacc[i][0] = fmaf(pf[i], v0.x, Oacc[i][0]);
                Oacc[i][1] = fmaf(pf[i], v0.y, Oacc[i][1]);
                Oacc[i][2] = fmaf(pf[i], v0.z, Oacc[i][2]);
                Oacc[i][3] = fmaf(pf[i], v0.w, Oacc[i][3]);
                Oacc[i][4] = fmaf(pf[i], v1.x, Oacc[i][4]);
                Oacc[i][5] = fmaf(pf[i], v1.y, Oacc[i][5]);
                Oacc[i][6] = fmaf(pf[i], v1.z, Oacc[i][6]);
                Oacc[i][7] = fmaf(pf[i], v1.w, Oacc[i][7]);
            }
        }
    }

    #pragma unroll
    for (int i = 0; i < 4; i++) {
        float linv = 1.f / rowl[orow + i];
        size_t off = ((size_t)b * NT + q0 + orow + i) * NC + h * ND + ocol;
        #pragma unroll
        for (int j = 0; j < 8; j += 2) {
            float v0 = Oacc[i][j] * linv, v1 = Oacc[i][j + 1] * linv;
            __nv_bfloat16 h0, l0, h1, l1;
            split_bf16(v0, h0, l0); split_bf16(v1, h1, l1);
            *(__nv_bfloat162*)&ahi[off + j] = __nv_bfloat162(h0, h1);
            *(__nv_bfloat162*)&alo[off + j] = __nv_bfloat162(l0, l1);
        }
    }
}

// ---------------------------------------------------------------------------
// Launch
// ---------------------------------------------------------------------------
static const int ATT_SMEM  = (64 * AQ_PAD * 2 + 64 * ND + 64 * AS_PAD + 192) * (int)sizeof(float);
static const int GEMM_SMEM = 2 * STAGE_B;   // 81920

extern "C" void kernel_launch(void* const* d_in, const int* in_sizes, int n_in,
                              void* d_out, int out_size) {
    const float* x      = (const float*)d_in[0];
    const float* rope   = (const float*)d_in[1];
    const float* ln1_w  = (const float*)d_in[2];
    const float* w_qkv  = (const float*)d_in[3];
    const float* qn_w   = (const float*)d_in[4];
    const float* kn_w   = (const float*)d_in[5];
    const float* w_out  = (const float*)d_in[6];
    const float* ln2_w  = (const float*)d_in[7];
    const float* w_fc1  = (const float*)d_in[8];
    const float* w_fc2  = (const float*)d_in[9];
    float* out = (float*)d_out;

    float *qkv, *q, *k, *v, *y1;
    __nv_bfloat16 *xnh, *xnl, *ath, *atl, *hh, *hl;
    __nv_bfloat16 *wqh, *wql, *woh, *wol, *w1h, *w1l, *w2h, *w2l;
    cudaGetSymbolAddress((void**)&xnh, g_xn_hi);
    cudaGetSymbolAddress((void**)&xnl, g_xn_lo);
    cudaGetSymbolAddress((void**)&qkv, g_qkv);
    cudaGetSymbolAddress((void**)&q,   g_q);
    cudaGetSymbolAddress((void**)&k,   g_k);
    cudaGetSymbolAddress((void**)&v,   g_v);
    cudaGetSymbolAddress((void**)&ath, g_at_hi);
    cudaGetSymbolAddress((void**)&atl, g_at_lo);
    cudaGetSymbolAddress((void**)&y1,  g_y1);
    cudaGetSymbolAddress((void**)&hh,  g_h_hi);
    cudaGetSymbolAddress((void**)&hl,  g_h_lo);
    cudaGetSymbolAddress((void**)&wqh, g_wqkvT_h);
    cudaGetSymbolAddress((void**)&wql, g_wqkvT_l);
    cudaGetSymbolAddress((void**)&woh, g_woutT_h);
    cudaGetSymbolAddress((void**)&wol, g_woutT_l);
    cudaGetSymbolAddress((void**)&w1h, g_wfc1T_h);
    cudaGetSymbolAddress((void**)&w1l, g_wfc1T_l);
    cudaGetSymbolAddress((void**)&w2h, g_wfc2T_h);
    cudaGetSymbolAddress((void**)&w2l, g_wfc2T_l);

    cudaFuncSetAttribute(attn_kernel, cudaFuncAttributeMaxDynamicSharedMemorySize, ATT_SMEM);
    cudaFuncSetAttribute(gemm_mma<0>, cudaFuncAttributeMaxDynamicSharedMemorySize, GEMM_SMEM);
    cudaFuncSetAttribute(gemm_mma<1>, cudaFuncAttributeMaxDynamicSharedMemorySize, GEMM_SMEM);
    cudaFuncSetAttribute(gemm_mma<2>, cudaFuncAttributeMaxDynamicSharedMemorySize, GEMM_SMEM);

    // Weight transpose+split
    wsplit<<<dim3(NC3 / 32, NC / 32), 256>>>(w_qkv, wqh, wql, NC, NC3);
    wsplit<<<dim3(NC  / 32, NC / 32), 256>>>(w_out, woh, wol, NC, NC);
    wsplit<<<dim3(NF  / 32, NC / 32), 256>>>(w_fc1, w1h, w1l, NC, NF);
    wsplit<<<dim3(NC  / 32, NF / 32), 256>>>(w_fc2, w2h, w2l, NF, NC);

    // 1) rmsnorm(x) -> hi/lo
    rmsnorm_split<<<NBT, 256>>>(x, ln1_w, xnh, xnl, NC);

    // 2) qkv = xn @ w_qkv (fp32 out)
    gemm_mma<0><<<dim3(NC3 / 128, NBT / 128), 256, GEMM_SMEM>>>(
        xnh, xnl, wqh, wql, nullptr, qkv, nullptr, nullptr, NBT, NC3, NC);

    // 3) RoPE + head rmsnorm + mxfp8 qdq
    qkv_post<<<NB * NT * NH, 128>>>(qkv, rope, qn_w, kn_w, q, k, v);

    // 4) causal attention -> hi/lo
    attn_kernel<<<dim3(NT / 64, NB * NH), 256, ATT_SMEM>>>(q, k, v, ath, atl);

    // 5) y1 = x + attn @ w_out
    gemm_mma<1><<<dim3(NC / 128, NBT / 128), 256, GEMM_SMEM>>>(
        ath, atl, woh, wol, x, y1, nullptr, nullptr, NBT, NC, NC);

    // 6) rmsnorm(y1) -> hi/lo
    rmsnorm_split<<<NBT, 256>>>(y1, ln2_w, xnh, xnl, NC);

    // 7) h = srelu(xn @ w_fc1) -> hi/lo
    gemm_mma<2><<<dim3(NF / 128, NBT / 128), 256, GEMM_SMEM>>>(
        xnh, xnl, w1h, w1l, nullptr, nullptr, hh, hl, NBT, NF, NC);

    // 8) out = y1 + h @ w_fc2
    gemm_mma<1><<<dim3(NC / 128, NBT / 128), 256, GEMM_SMEM>>>(
        hh, hl, w2h, w2l, y1, out, nullptr, nullptr, NBT, NC, NF);
}

// round 5
// speedup vs baseline: 3.1553x; 1.4507x over previous
#include <cuda_runtime.h>
#include <cuda_bf16.h>
#include <cuda_fp8.h>
#include <math.h>
#include <stdint.h>

// Problem constants
#define NB 4
#define NT 2048
#define NC 1280
#define NH 10
#define ND 128
#define NF 5120
#define NBT (NB*NT)          // 8192
#define NC3 (3*NC)           // 3840
#define EPSF 1e-5f
#define ATT_SCALE 0.08838834764831845f   // 1/sqrt(128)

// ---------------------------------------------------------------------------
// Scratch (device globals — allocation-free per harness rules)
// ---------------------------------------------------------------------------
__device__ __nv_bfloat16 g_xn_hi[(size_t)NBT * NC];
__device__ __nv_bfloat16 g_xn_lo[(size_t)NBT * NC];
__device__ float g_qkv[(size_t)NBT * NC3];
__device__ __nv_bfloat16 g_qb[(size_t)NB * NH * NT * ND];
__device__ __nv_bfloat16 g_kb[(size_t)NB * NH * NT * ND];
__device__ __nv_bfloat16 g_vb[(size_t)NB * NH * NT * ND];
__device__ __nv_bfloat16 g_at_hi[(size_t)NBT * NC];
__device__ __nv_bfloat16 g_at_lo[(size_t)NBT * NC];
__device__ float g_y1 [(size_t)NBT * NC];
__device__ __nv_bfloat16 g_h_hi[(size_t)NBT * NF];
__device__ __nv_bfloat16 g_h_lo[(size_t)NBT * NF];
// transposed+split weights [N,K]
__device__ __nv_bfloat16 g_wqkvT_h[(size_t)NC3 * NC];
__device__ __nv_bfloat16 g_wqkvT_l[(size_t)NC3 * NC];
__device__ __nv_bfloat16 g_woutT_h[(size_t)NC * NC];
__device__ __nv_bfloat16 g_woutT_l[(size_t)NC * NC];
__device__ __nv_bfloat16 g_wfc1T_h[(size_t)NF * NC];
__device__ __nv_bfloat16 g_wfc1T_l[(size_t)NF * NC];
__device__ __nv_bfloat16 g_wfc2T_h[(size_t)NC * NF];
__device__ __nv_bfloat16 g_wfc2T_l[(size_t)NC * NF];

// ---------------------------------------------------------------------------
// PTX helpers (baseline ISA: cp.async / ldmatrix / mma.sync)
// ---------------------------------------------------------------------------
__device__ __forceinline__ uint32_t smem_u32(const void* p) {
    uint32_t a;
    asm("{ .reg .u64 t; cvta.to.shared.u64 t, %1; cvt.u32.u64 %0, t; }" : "=r"(a) : "l"(p));
    return a;
}
__device__ __forceinline__ void cp16(uint32_t dst, const void* src) {
    asm volatile("cp.async.cg.shared.global [%0], [%1], 16;" :: "r"(dst), "l"(src));
}
__device__ __forceinline__ void ldsm_x4(uint32_t& r0, uint32_t& r1, uint32_t& r2,
                                        uint32_t& r3, uint32_t addr) {
    asm volatile("ldmatrix.sync.aligned.m8n8.x4.shared.b16 {%0,%1,%2,%3}, [%4];"
                 : "=r"(r0), "=r"(r1), "=r"(r2), "=r"(r3) : "r"(addr));
}
__device__ __forceinline__ void ldsm_x4t(uint32_t& r0, uint32_t& r1, uint32_t& r2,
                                         uint32_t& r3, uint32_t addr) {
    asm volatile("ldmatrix.sync.aligned.m8n8.x4.trans.shared.b16 {%0,%1,%2,%3}, [%4];"
                 : "=r"(r0), "=r"(r1), "=r"(r2), "=r"(r3) : "r"(addr));
}
__device__ __forceinline__ void mma16816(float* c, const uint32_t* a,
                                         uint32_t b0, uint32_t b1) {
    asm volatile(
        "mma.sync.aligned.m16n8k16.row.col.f32.bf16.bf16.f32 "
        "{%0,%1,%2,%3}, {%4,%5,%6,%7}, {%8,%9}, {%0,%1,%2,%3};"
        : "+f"(c[0]), "+f"(c[1]), "+f"(c[2]), "+f"(c[3])
        : "r"(a[0]), "r"(a[1]), "r"(a[2]), "r"(a[3]), "r"(b0), "r"(b1));
}

// ---------------------------------------------------------------------------
// hi/lo bf16 split
// ---------------------------------------------------------------------------
__device__ __forceinline__ void split_bf16(float v, __nv_bfloat16& h, __nv_bfloat16& l) {
    h = __float2bfloat16(v);
    l = __float2bfloat16(v - __bfloat162float(h));
}
__device__ __forceinline__ uint32_t pack_bf(__nv_bfloat16 lo, __nv_bfloat16 hi) {
    __nv_bfloat162 t(lo, hi);   // .x in low 16 bits
    return *(uint32_t*)&t;
}

// ---------------------------------------------------------------------------
// RMSNorm -> hi/lo bf16 split. One block (256 threads) per row.
// ---------------------------------------------------------------------------
__global__ __launch_bounds__(256)
void rmsnorm_split(const float* __restrict__ in, const float* __restrict__ w,
                   __nv_bfloat16* __restrict__ ohi, __nv_bfloat16* __restrict__ olo,
                   int ncols) {
    int row = blockIdx.x;
    const float* p = in + (size_t)row * ncols;
    size_t ob = (size_t)row * ncols;
    float ss = 0.f;
    for (int c = threadIdx.x; c < ncols; c += 256) { float v = p[c]; ss = fmaf(v, v, ss); }
    #pragma unroll
    for (int off = 16; off; off >>= 1) ss += __shfl_xor_sync(0xffffffffu, ss, off);
    __shared__ float red[8];
    int wid = threadIdx.x >> 5, lane = threadIdx.x & 31;
    if (lane == 0) red[wid] = ss;
    __syncthreads();
    float tot = 0.f;
    #pragma unroll
    for (int i = 0; i < 8; i++) tot += red[i];
    float r = rsqrtf(tot / (float)ncols + EPSF);
    for (int c = threadIdx.x; c < ncols; c += 256) {
        float v = p[c] * r * w[c];
        __nv_bfloat16 h, l; split_bf16(v, h, l);
        ohi[ob + c] = h; olo[ob + c] = l;
    }
}

// ---------------------------------------------------------------------------
// Weight transpose + split: W [K,N] fp32 -> Thi/Tlo [N,K] bf16
// ---------------------------------------------------------------------------
__global__ __launch_bounds__(256)
void wsplit(const float* __restrict__ W, __nv_bfloat16* __restrict__ Thi,
            __nv_bfloat16* __restrict__ Tlo, int K, int N) {
    __shared__ float t[32][33];
    int n0 = blockIdx.x * 32, k0 = blockIdx.y * 32;
    int tx = threadIdx.x & 31, ty = threadIdx.x >> 5;
    #pragma unroll
    for (int i = 0; i < 4; i++) {
        int k = ty + i * 8;
        t[k][tx] = W[(size_t)(k0 + k) * N + n0 + tx];
    }
    __syncthreads();
    #pragma unroll
    for (int i = 0; i < 4; i++) {
        int n = ty + i * 8;
        float v = t[tx][n];
        __nv_bfloat16 h, l; split_bf16(v, h, l);
        Thi[(size_t)(n0 + n) * K + k0 + tx] = h;
        Tlo[(size_t)(n0 + n) * K + k0 + tx] = l;
    }
}

// ---------------------------------------------------------------------------
// mma.sync bf16 GEMM with 3-term hi/lo split (unchanged from R3)
// ---------------------------------------------------------------------------
#define APAD 40
#define TILE_B (128 * APAD * 2)
#define STAGE_B (4 * TILE_B)

__device__ __forceinline__ void gemm_load_stage(
    uint32_t st, const char* Ah, const char* Al, const char* Bh, const char* Bl,
    size_t rowb, size_t ko, int tid) {
    #pragma unroll
    for (int i = 0; i < 2; i++) {
        int idx = tid + i * 256;
        int r = idx >> 2, c = idx & 3;
        uint32_t dst = st + (uint32_t)(r * 80 + c * 16);
        size_t src = (size_t)r * rowb + ko + (size_t)c * 16;
        cp16(dst + 0u * TILE_B, Ah + src);
        cp16(dst + 1u * TILE_B, Al + src);
        cp16(dst + 2u * TILE_B, Bh + src);
        cp16(dst + 3u * TILE_B, Bl + src);
    }
    asm volatile("cp.async.commit_group;" ::: "memory");
}

template <int MODE>
__global__ __launch_bounds__(256)
void gemm_mma(const __nv_bfloat16* __restrict__ Ahi, const __nv_bfloat16* __restrict__ Alo,
              const __nv_bfloat16* __restrict__ Bhi, const __nv_bfloat16* __restrict__ Blo,
              const float* __restrict__ Res, float* __restrict__ Cf,
              __nv_bfloat16* __restrict__ Chi, __nv_bfloat16* __restrict__ Clo,
              int M, int N, int K) {
    extern __shared__ char smem[];
    const uint32_t sb = smem_u32(smem);
    const int tid  = threadIdx.x;
    const int warp = tid >> 5, lane = tid & 31;
    const int warp_m = warp & 3;
    const int warp_n = warp >> 2;
    const int bm = blockIdx.y << 7;
    const int bn = blockIdx.x << 7;

    float acc[2][8][4];
    #pragma unroll
    for (int i = 0; i < 2; i++)
        #pragma unroll
        for (int j = 0; j < 8; j++)
            #pragma unroll
            for (int q = 0; q < 4; q++) acc[i][j][q] = 0.f;

    const size_t rowb = (size_t)K * 2;
    const char* Ah0 = (const char*)Ahi + (size_t)bm * rowb;
    const char* Al0 = (const char*)Alo + (size_t)bm * rowb;
    const char* Bh0 = (const char*)Bhi + (size_t)bn * rowb;
    const char* Bl0 = (const char*)Blo + (size_t)bn * rowb;

    const int NIT = K >> 5;

    gemm_load_stage(sb, Ah0, Al0, Bh0, Bl0, rowb, 0, tid);

    const int arow = warp_m * 32 + (lane & 15);
    const int acolb = ((lane >> 4) << 3);
    const int brow = warp_n * 64 + (lane & 7) + ((lane >> 4) << 3);
    const int bcolb = (lane & 8);

    for (int it = 0; it < NIT; it++) {
        if (it + 1 < NIT)
            gemm_load_stage(sb + (uint32_t)(((it + 1) & 1) * STAGE_B),
                            Ah0, Al0, Bh0, Bl0, rowb, (size_t)(it + 1) * 64, tid);
        if (it + 1 < NIT)
            asm volatile("cp.async.wait_group 1;" ::: "memory");
        else
            asm volatile("cp.async.wait_group 0;" ::: "memory");
        __syncthreads();

        const uint32_t st  = sb + (uint32_t)((it & 1) * STAGE_B);
        const uint32_t sah = st;
        const uint32_t sal = st + TILE_B;
        const uint32_t sbh = st + 2u * TILE_B;
        const uint32_t sbl = st + 3u * TILE_B;

        #pragma unroll
        for (int ks = 0; ks < 2; ks++) {
            uint32_t ah[2][4], al[2][4], bh[4][4], bl[4][4];
            const int acol = ks * 16 + acolb;
            const int bcol = ks * 16 + bcolb;
            #pragma unroll
            for (int mi = 0; mi < 2; mi++) {
                uint32_t off = (uint32_t)(((arow + mi * 16) * APAD + acol) * 2);
                ldsm_x4(ah[mi][0], ah[mi][1], ah[mi][2], ah[mi][3], sah + off);
                ldsm_x4(al[mi][0], al[mi][1], al[mi][2], al[mi][3], sal + off);
            }
            #pragma unroll
            for (int ni = 0; ni < 4; ni++) {
                uint32_t off = (uint32_t)(((brow + ni * 16) * APAD + bcol) * 2);
                ldsm_x4(bh[ni][0], bh[ni][1], bh[ni][2], bh[ni][3], sbh + off);
                ldsm_x4(bl[ni][0], bl[ni][1], bl[ni][2], bl[ni][3], sbl + off);
            }
            #pragma unroll
            for (int mi = 0; mi < 2; mi++) {
                #pragma unroll
                for (int ni = 0; ni < 4; ni++) {
                    mma16816(acc[mi][2 * ni],     ah[mi], bh[ni][0], bh[ni][1]);
                    mma16816(acc[mi][2 * ni + 1], ah[mi], bh[ni][2], bh[ni][3]);
                    mma16816(acc[mi][2 * ni],     ah[mi], bl[ni][0], bl[ni][1]);
                    mma16816(acc[mi][2 * ni + 1], ah[mi], bl[ni][2], bl[ni][3]);
                    mma16816(acc[mi][2 * ni],     al[mi], bh[ni][0], bh[ni][1]);
                    mma16816(acc[mi][2 * ni + 1], al[mi], bh[ni][2], bh[ni][3]);
                }
            }
        }
        __syncthreads();
    }

    const int r0 = bm + warp_m * 32 + (lane >> 2);
    const int c0 = bn + warp_n * 64 + 2 * (lane & 3);
    #pragma unroll
    for (int mi = 0; mi < 2; mi++) {
        #pragma unroll
        for (int half = 0; half < 2; half++) {
            int row = r0 + mi * 16 + half * 8;
            size_t rb = (size_t)row * N;
            #pragma unroll
            for (int nj = 0; nj < 8; nj++) {
                int col = c0 + nj * 8;
                float v0 = acc[mi][nj][2 * half];
                float v1 = acc[mi][nj][2 * half + 1];
                size_t o = rb + col;
                if (MODE == 0) {
                    *(float2*)&Cf[o] = make_float2(v0, v1);
                } else if (MODE == 1) {
                    float2 rv = *(const float2*)&Res[o];
                    *(float2*)&Cf[o] = make_float2(v0 + rv.x, v1 + rv.y);
                } else {
                    float t0 = fmaxf(v0, 0.f); v0 = t0 * t0;
                    float t1 = fmaxf(v1, 0.f); v1 = t1 * t1;
                    __nv_bfloat16 h0, l0, h1, l1;
                    split_bf16(v0, h0, l0); split_bf16(v1, h1, l1);
                    *(__nv_bfloat162*)&Chi[o] = __nv_bfloat162(h0, h1);
                    *(__nv_bfloat162*)&Clo[o] = __nv_bfloat162(l0, l1);
                }
            }
        }
    }
}

// ---------------------------------------------------------------------------
// MXFP8 qdq (32-element block == one warp)
// ---------------------------------------------------------------------------
__device__ __forceinline__ float qdq32(float x) {
    float a = fabsf(x);
    #pragma unroll
    for (int off = 16; off; off >>= 1) a = fmaxf(a, __shfl_xor_sync(0xffffffffu, a, off));
    a = fmaxf(a, 1e-12f);
    int se = ilogbf(a) + 119;
    se = max(0, min(255, se));
    float scale = exp2f((float)(127 - se));
    float xs = fminf(fmaxf(x * scale, -448.f), 448.f);
    float xq = (float)__nv_fp8_e4m3(xs);
    return xq * exp2f((float)(se - 127));
}

// ---------------------------------------------------------------------------
// QKV post-process: RoPE -> head rmsnorm -> qdq -> (b,h,t,d) bf16 (exact)
// ---------------------------------------------------------------------------
__global__ __launch_bounds__(128)
void qkv_post(const float* __restrict__ qkv, const float* __restrict__ rope,
              const float* __restrict__ qn_w, const float* __restrict__ kn_w,
              __nv_bfloat16* __restrict__ gq, __nv_bfloat16* __restrict__ gk,
              __nv_bfloat16* __restrict__ gv) {
    int idx = blockIdx.x;
    int h  = idx % NH;
    int bt = idx / NH;
    int t  = bt % NT;
    int b  = bt / NT;
    int d  = threadIdx.x;

    const float* base = qkv + (size_t)bt * NC3 + h * ND;
    float qv = base[d];
    float kv = base[NC + d];
    float vv = base[2 * NC + d];

    float fr = rope[t * ND + d];
    float sn, cs;
    sincosf(fr, &sn, &cs);
    __shared__ float sq[ND], sk[ND];
    sq[d] = qv; sk[d] = kv;
    __syncthreads();
    float qr = (d < 64) ? -sq[d + 64] : sq[d - 64];
    float kr = (d < 64) ? -sk[d + 64] : sk[d - 64];
    qv = qv * cs + qr * sn;
    kv = kv * cs + kr * sn;

    float s1 = qv * qv, s2 = kv * kv;
    #pragma unroll
    for (int off = 16; off; off >>= 1) {
        s1 += __shfl_xor_sync(0xffffffffu, s1, off);
        s2 += __shfl_xor_sync(0xffffffffu, s2, off);
    }
    __shared__ float r1[4], r2[4];
    int w = d >> 5, lane = d & 31;
    if (lane == 0) { r1[w] = s1; r2[w] = s2; }
    __syncthreads();
    float ssq = r1[0] + r1[1] + r1[2] + r1[3];
    float ssk = r2[0] + r2[1] + r2[2] + r2[3];
    qv *= rsqrtf(ssq * (1.f / ND) + EPSF) * qn_w[d];
    kv *= rsqrtf(ssk * (1.f / ND) + EPSF) * kn_w[d];

    qv = qdq32(qv);
    kv = qdq32(kv);
    vv = qdq32(vv);

    size_t o = (((size_t)(b * NH + h)) * NT + t) * ND + d;
    gq[o] = __float2bfloat16(qv);   // exact: qdq values have <=4 mantissa bits
    gk[o] = __float2bfloat16(kv);
    gv[o] = __float2bfloat16(vv);
}

// ---------------------------------------------------------------------------
// Tensor-core causal flash attention (FA2 style, mma.sync bf16).
// CTA: 128 q-rows, 8 warps x 16 rows. k-tiles of 64, D=128.
// S = Q K^T exact (qdq values exact in bf16); P hi/lo split for P@V.
// ---------------------------------------------------------------------------
#define DP 136                        // padded row length (bf16 elems)
#define ATT_Q_ELEMS (128 * DP)        // 17408
#define ATT_T_ELEMS (64 * DP)         // 8704
#define ATT_SMEM2 ((ATT_Q_ELEMS + 4 * ATT_T_ELEMS) * 2)   // 104448 bytes

__device__ __forceinline__ void att_load_kv(uint32_t sK, uint32_t sV,
                                            const __nv_bfloat16* Kg,
                                            const __nv_bfloat16* Vg,
                                            int kb, int tid) {
    #pragma unroll
    for (int i = 0; i < 4; i++) {
        int idx = tid + i * 256;
        int r = idx >> 4, c = (idx & 15) << 3;
        uint32_t d = (uint32_t)((r * DP + c) * 2);
        cp16(sK + d, Kg + (size_t)(kb + r) * ND + c);
        cp16(sV + d, Vg + (size_t)(kb + r) * ND + c);
    }
    asm volatile("cp.async.commit_group;" ::: "memory");
}

__global__ __launch_bounds__(256)
void attn_mma(const __nv_bfloat16* __restrict__ gq, const __nv_bfloat16* __restrict__ gk,
              const __nv_bfloat16* __restrict__ gv,
              __nv_bfloat16* __restrict__ ahi, __nv_bfloat16* __restrict__ alo) {
    extern __shared__ char sm2[];
    const uint32_t sQ = smem_u32(sm2);
    const uint32_t sKV = sQ + ATT_Q_ELEMS * 2;

    const int tid  = threadIdx.x;
    const int warp = tid >> 5, lane = tid & 31;
    const int g  = lane >> 2, qr = lane & 3;
    const int qblk = blockIdx.x;
    const int q0   = qblk << 7;
    const int bh   = blockIdx.y;
    const int b    = bh / NH, h = bh % NH;

    const __nv_bfloat16* Qg = gq + ((size_t)bh * NT + q0) * ND;
    const __nv_bfloat16* Kg = gk + (size_t)bh * NT * ND;
    const __nv_bfloat16* Vg = gv + (size_t)bh * NT * ND;

    // stage Q (128x128) into smem
    #pragma unroll
    for (int i = 0; i < 8; i++) {
        int idx = tid + i * 256;
        int r = idx >> 4, c = (idx & 15) << 3;
        cp16(sQ + (uint32_t)((r * DP + c) * 2), Qg + (size_t)r * ND + c);
    }
    asm volatile("cp.async.commit_group;" ::: "memory");
    att_load_kv(sKV, sKV + ATT_T_ELEMS * 2, Kg, Vg, 0, tid);
    asm volatile("cp.async.wait_group 0;" ::: "memory");
    __syncthreads();

    // Q fragments (register resident)
    uint32_t qa[8][4];
    {
        const uint32_t qbase = sQ + (uint32_t)(((warp * 16 + (lane & 15)) * DP
                                                + ((lane >> 4) << 3)) * 2);
        #pragma unroll
        for (int ks = 0; ks < 8; ks++)
            ldsm_x4(qa[ks][0], qa[ks][1], qa[ks][2], qa[ks][3], qbase + ks * 32);
    }

    float oc[16][4];
    #pragma unroll
    for (int i = 0; i < 16; i++)
        #pragma unroll
        for (int j = 0; j < 4; j++) oc[i][j] = 0.f;
    float m0 = -INFINITY, m1 = -INFINITY, l0 = 0.f, l1 = 0.f;
    const int row0 = q0 + warp * 16 + g;
    const int row1 = row0 + 8;
    const int wrow_max = q0 + warp * 16 + 15;

    const int nkt = 2 * qblk + 2;
    for (int kt = 0; kt < nkt; kt++) {
        if (kt + 1 < nkt)
            att_load_kv(sKV + (uint32_t)(((kt + 1) & 1) * 2 * ATT_T_ELEMS * 2),
                        sKV + (uint32_t)((((kt + 1) & 1) * 2 + 1) * ATT_T_ELEMS * 2),
                        Kg, Vg, (kt + 1) << 6, tid);

        const int kb = kt << 6;
        if (kb <= wrow_max) {
            const uint32_t sK = sKV + (uint32_t)((kt & 1) * 2 * ATT_T_ELEMS * 2);
            const uint32_t sV = sK + (uint32_t)(ATT_T_ELEMS * 2);

            // S = Q K^T (8 n-tiles x 8 k-steps)
            float s[8][4];
            #pragma unroll
            for (int j = 0; j < 8; j++)
                #pragma unroll
                for (int q = 0; q < 4; q++) s[j][q] = 0.f;
            #pragma unroll
            for (int np = 0; np < 4; np++) {
                const uint32_t ka = sK + (uint32_t)(((np * 16 + (lane & 7)
                                  + ((lane >> 4) << 3)) * DP + (((lane >> 3) & 1) << 3)) * 2);
                #pragma unroll
                for (int ks = 0; ks < 8; ks++) {
                    uint32_t b0, b1, b2, b3;
                    ldsm_x4(b0, b1, b2, b3, ka + ks * 32);
                    mma16816(s[2 * np],     qa[ks], b0, b1);
                    mma16816(s[2 * np + 1], qa[ks], b2, b3);
                }
            }

            // scale + causal mask + row max
            float mx0 = -INFINITY, mx1 = -INFINITY;
            #pragma unroll
            for (int j = 0; j < 8; j++) {
                int c0 = kb + j * 8 + qr * 2;
                s[j][0] = (c0     <= row0) ? s[j][0] * ATT_SCALE : -INFINITY;
                s[j][1] = (c0 + 1 <= row0) ? s[j][1] * ATT_SCALE : -INFINITY;
                s[j][2] = (c0     <= row1) ? s[j][2] * ATT_SCALE : -INFINITY;
                s[j][3] = (c0 + 1 <= row1) ? s[j][3] * ATT_SCALE : -INFINITY;
                mx0 = fmaxf(mx0, fmaxf(s[j][0], s[j][1]));
                mx1 = fmaxf(mx1, fmaxf(s[j][2], s[j][3]));
            }
            mx0 = fmaxf(mx0, __shfl_xor_sync(0xffffffffu, mx0, 1));
            mx0 = fmaxf(mx0, __shfl_xor_sync(0xffffffffu, mx0, 2));
            mx1 = fmaxf(mx1, __shfl_xor_sync(0xffffffffu, mx1, 1));
            mx1 = fmaxf(mx1, __shfl_xor_sync(0xffffffffu, mx1, 2));

            float mn0 = fmaxf(m0, mx0), mn1 = fmaxf(m1, mx1);
            float al0 = __expf(m0 - mn0), al1 = __expf(m1 - mn1);
            m0 = mn0; m1 = mn1;

            // exp -> P (hi/lo packed bf16 fragments)
            uint32_t phi[8][2], plo[8][2];
            float ls0 = 0.f, ls1 = 0.f;
            #pragma unroll
            for (int j = 0; j < 8; j++) {
                float p0 = __expf(s[j][0] - mn0);
                float p1 = __expf(s[j][1] - mn0);
                float p2 = __expf(s[j][2] - mn1);
                float p3 = __expf(s[j][3] - mn1);
                ls0 += p0 + p1; ls1 += p2 + p3;
                __nv_bfloat16 h0, lw0, h1, lw1, h2, lw2, h3, lw3;
                split_bf16(p0, h0, lw0); split_bf16(p1, h1, lw1);
                split_bf16(p2, h2, lw2); split_bf16(p3, h3, lw3);
                phi[j][0] = pack_bf(h0, h1);  phi[j][1] = pack_bf(h2, h3);
                plo[j][0] = pack_bf(lw0, lw1); plo[j][1] = pack_bf(lw2, lw3);
            }
            l0 = l0 * al0 + ls0;
            l1 = l1 * al1 + ls1;

            // rescale O
            #pragma unroll
            for (int nt = 0; nt < 16; nt++) {
                oc[nt][0] *= al0; oc[nt][1] *= al0;
                oc[nt][2] *= al1; oc[nt][3] *= al1;
            }

            // O += P V  (4 k-steps x 8 n-pairs, hi+lo)
            #pragma unroll
            for (int ks = 0; ks < 4; ks++) {
                uint32_t ah[4] = { phi[2*ks][0], phi[2*ks][1], phi[2*ks+1][0], phi[2*ks+1][1] };
                uint32_t alw[4] = { plo[2*ks][0], plo[2*ks][1], plo[2*ks+1][0], plo[2*ks+1][1] };
                const uint32_t va0 = sV + (uint32_t)(((ks * 16 + (lane & 7)
                                   + ((lane >> 3) & 1) * 8) * DP + ((lane >> 4) << 3)) * 2);
                #pragma unroll
                for (int np = 0; np < 8; np++) {
                    uint32_t b0, b1, b2, b3;
                    ldsm_x4t(b0, b1, b2, b3, va0 + np * 32);
                    mma16816(oc[2 * np],     ah,  b0, b1);
                    mma16816(oc[2 * np + 1], ah,  b2, b3);
                    mma16816(oc[2 * np],     alw, b0, b1);
                    mma16816(oc[2 * np + 1], alw, b2, b3);
                }
            }
        }

        if (kt + 1 < nkt)
            asm volatile("cp.async.wait_group 0;" ::: "memory");
        __syncthreads();
    }

    // FIX (R4 bug): l0/l1 are per-lane partial sums over the quad's column
    // subset; m was quad-reduced so a single sum-reduction across the quad
    // yields the exact row sum.
    l0 += __shfl_xor_sync(0xffffffffu, l0, 1);
    l0 += __shfl_xor_sync(0xffffffffu, l0, 2);
    l1 += __shfl_xor_sync(0xffffffffu, l1, 1);
    l1 += __shfl_xor_sync(0xffffffffu, l1, 2);

    // epilogue: normalize, hi/lo split, write (b, t, h*128 + d)
    const float li0 = 1.f / l0, li1 = 1.f / l1;
    const size_t ob0 = ((size_t)b * NT + row0) * NC + h * ND;
    const size_t ob1 = ((size_t)b * NT + row1) * NC + h * ND;
    #pragma unroll
    for (int nt = 0; nt < 16; nt++) {
        int col = nt * 8 + qr * 2;
        float v0 = oc[nt][0] * li0, v1 = oc[nt][1] * li0;
        float v2 = oc[nt][2] * li1, v3 = oc[nt][3] * li1;
        __nv_bfloat16 h0, lw0, h1, lw1, h2, lw2, h3, lw3;
        split_bf16(v0, h0, lw0); split_bf16(v1, h1, lw1);
        split_bf16(v2, h2, lw2); split_bf16(v3, h3, lw3);
        *(__nv_bfloat162*)&ahi[ob0 + col] = __nv_bfloat162(h0, h1);
        *(__nv_bfloat162*)&alo[ob0 + col] = __nv_bfloat162(lw0, lw1);
        *(__nv_bfloat162*)&ahi[ob1 + col] = __nv_bfloat162(h2, h3);
        *(__nv_bfloat162*)&alo[ob1 + col] = __nv_bfloat162(lw2, lw3);
    }
}

// ---------------------------------------------------------------------------
// Launch
// ---------------------------------------------------------------------------
static const int GEMM_SMEM = 2 * STAGE_B;

extern "C" void kernel_launch(void* const* d_in, const int* in_sizes, int n_in,
                              void* d_out, int out_size) {
    const float* x      = (const float*)d_in[0];
    const float* rope   = (const float*)d_in[1];
    const float* ln1_w  = (const float*)d_in[2];
    const float* w_qkv  = (const float*)d_in[3];
    const float* qn_w   = (const float*)d_in[4];
    const float* kn_w   = (const float*)d_in[5];
    const float* w_out  = (const float*)d_in[6];
    const float* ln2_w  = (const float*)d_in[7];
    const float* w_fc1  = (const float*)d_in[8];
    const float* w_fc2  = (const float*)d_in[9];
    float* out = (float*)d_out;

    float *qkv, *y1;
    __nv_bfloat16 *xnh, *xnl, *qb, *kb, *vb, *ath, *atl, *hh, *hl;
    __nv_bfloat16 *wqh, *wql, *woh, *wol, *w1h, *w1l, *w2h, *w2l;
    cudaGetSymbolAddress((void**)&xnh, g_xn_hi);
    cudaGetSymbolAddress((void**)&xnl, g_xn_lo);
    cudaGetSymbolAddress((void**)&qkv, g_qkv);
    cudaGetSymbolAddress((void**)&qb,  g_qb);
    cudaGetSymbolAddress((void**)&kb,  g_kb);
    cudaGetSymbolAddress((void**)&vb,  g_vb);
    cudaGetSymbolAddress((void**)&ath, g_at_hi);
    cudaGetSymbolAddress((void**)&atl, g_at_lo);
    cudaGetSymbolAddress((void**)&y1,  g_y1);
    cudaGetSymbolAddress((void**)&hh,  g_h_hi);
    cudaGetSymbolAddress((void**)&hl,  g_h_lo);
    cudaGetSymbolAddress((void**)&wqh, g_wqkvT_h);
    cudaGetSymbolAddress((void**)&wql, g_wqkvT_l);
    cudaGetSymbolAddress((void**)&woh, g_woutT_h);
    cudaGetSymbolAddress((void**)&wol, g_woutT_l);
    cudaGetSymbolAddress((void**)&w1h, g_wfc1T_h);
    cudaGetSymbolAddress((void**)&w1l, g_wfc1T_l);
    cudaGetSymbolAddress((void**)&w2h, g_wfc2T_h);
    cudaGetSymbolAddress((void**)&w2l, g_wfc2T_l);

    cudaFuncSetAttribute(attn_mma, cudaFuncAttributeMaxDynamicSharedMemorySize, ATT_SMEM2);
    cudaFuncSetAttribute(gemm_mma<0>, cudaFuncAttributeMaxDynamicSharedMemorySize, GEMM_SMEM);
    cudaFuncSetAttribute(gemm_mma<1>, cudaFuncAttributeMaxDynamicSharedMemorySize, GEMM_SMEM);
    cudaFuncSetAttribute(gemm_mma<2>, cudaFuncAttributeMaxDynamicSharedMemorySize, GEMM_SMEM);

    // Weight transpose+split
    wsplit<<<dim3(NC3 / 32, NC / 32), 256>>>(w_qkv, wqh, wql, NC, NC3);
    wsplit<<<dim3(NC  / 32, NC / 32), 256>>>(w_out, woh, wol, NC, NC);
    wsplit<<<dim3(NF  / 32, NC / 32), 256>>>(w_fc1, w1h, w1l, NC, NF);
    wsplit<<<dim3(NC  / 32, NF / 32), 256>>>(w_fc2, w2h, w2l, NF, NC);

    // 1) rmsnorm(x) -> hi/lo
    rmsnorm_split<<<NBT, 256>>>(x, ln1_w, xnh, xnl, NC);

    // 2) qkv = xn @ w_qkv (fp32 out)
    gemm_mma<0><<<dim3(NC3 / 128, NBT / 128), 256, GEMM_SMEM>>>(
        xnh, xnl, wqh, wql, nullptr, qkv, nullptr, nullptr, NBT, NC3, NC);

    // 3) RoPE + head rmsnorm + mxfp8 qdq -> bf16 (exact)
    qkv_post<<<NB * NT * NH, 128>>>(qkv, rope, qn_w, kn_w, qb, kb, vb);

    // 4) tensor-core causal attention -> hi/lo
    attn_mma<<<dim3(NT / 128, NB * NH), 256, ATT_SMEM2>>>(qb, kb, vb, ath, atl);

    // 5) y1 = x + attn @ w_out
    gemm_mma<1><<<dim3(NC / 128, NBT / 128), 256, GEMM_SMEM>>>(
        ath, atl, woh, wol, x, y1, nullptr, nullptr, NBT, NC, NC);

    // 6) rmsnorm(y1) -> hi/lo
    rmsnorm_split<<<NBT, 256>>>(y1, ln2_w, xnh, xnl, NC);

    // 7) h = srelu(xn @ w_fc1) -> hi/lo
    gemm_mma<2><<<dim3(NF / 128, NBT / 128), 256, GEMM_SMEM>>>(
        xnh, xnl, w1h, w1l, nullptr, nullptr, hh, hl, NBT, NF, NC);

    // 8) out = y1 + h @ w_fc2
    gemm_mma<1><<<dim3(NC / 128, NBT / 128), 256, GEMM_SMEM>>>(
        hh, hl, w2h, w2l, y1, out, nullptr, nullptr, NBT, NC, NF);
}

// round 6
// speedup vs baseline: 3.2244x; 1.0219x over previous
#include <cuda_runtime.h>
#include <cuda_bf16.h>
#include <cuda_fp16.h>
#include <cuda_fp8.h>
#include <math.h>
#include <stdint.h>

// Problem constants
#define NB 4
#define NT 2048
#define NC 1280
#define NH 10
#define ND 128
#define NF 5120
#define NBT (NB*NT)          // 8192
#define NC3 (3*NC)           // 3840
#define EPSF 1e-5f
#define ATT_SCALE 0.08838834764831845f   // 1/sqrt(128)

// ---------------------------------------------------------------------------
// Scratch (device globals — allocation-free per harness rules)
// ---------------------------------------------------------------------------
__device__ __nv_bfloat16 g_xn_hi[(size_t)NBT * NC];
__device__ __nv_bfloat16 g_xn_lo[(size_t)NBT * NC];
__device__ float g_qkv[(size_t)NBT * NC3];
__device__ __half g_qb[(size_t)NB * NH * NT * ND];
__device__ __half g_kb[(size_t)NB * NH * NT * ND];
__device__ __half g_vb[(size_t)NB * NH * NT * ND];
__device__ __nv_bfloat16 g_at_hi[(size_t)NBT * NC];
__device__ __nv_bfloat16 g_at_lo[(size_t)NBT * NC];
__device__ float g_y1 [(size_t)NBT * NC];
__device__ __nv_bfloat16 g_h_hi[(size_t)NBT * NF];
__device__ __nv_bfloat16 g_h_lo[(size_t)NBT * NF];
// transposed+split weights [N,K]
__device__ __nv_bfloat16 g_wqkvT_h[(size_t)NC3 * NC];
__device__ __nv_bfloat16 g_wqkvT_l[(size_t)NC3 * NC];
__device__ __nv_bfloat16 g_woutT_h[(size_t)NC * NC];
__device__ __nv_bfloat16 g_woutT_l[(size_t)NC * NC];
__device__ __nv_bfloat16 g_wfc1T_h[(size_t)NF * NC];
__device__ __nv_bfloat16 g_wfc1T_l[(size_t)NF * NC];
__device__ __nv_bfloat16 g_wfc2T_h[(size_t)NC * NF];
__device__ __nv_bfloat16 g_wfc2T_l[(size_t)NC * NF];

// ---------------------------------------------------------------------------
// PTX helpers (baseline ISA: cp.async / ldmatrix / mma.sync)
// ---------------------------------------------------------------------------
__device__ __forceinline__ uint32_t smem_u32(const void* p) {
    uint32_t a;
    asm("{ .reg .u64 t; cvta.to.shared.u64 t, %1; cvt.u32.u64 %0, t; }" : "=r"(a) : "l"(p));
    return a;
}
__device__ __forceinline__ void cp16(uint32_t dst, const void* src) {
    asm volatile("cp.async.cg.shared.global [%0], [%1], 16;" :: "r"(dst), "l"(src));
}
__device__ __forceinline__ void ldsm_x4(uint32_t& r0, uint32_t& r1, uint32_t& r2,
                                        uint32_t& r3, uint32_t addr) {
    asm volatile("ldmatrix.sync.aligned.m8n8.x4.shared.b16 {%0,%1,%2,%3}, [%4];"
                 : "=r"(r0), "=r"(r1), "=r"(r2), "=r"(r3) : "r"(addr));
}
__device__ __forceinline__ void ldsm_x4t(uint32_t& r0, uint32_t& r1, uint32_t& r2,
                                         uint32_t& r3, uint32_t addr) {
    asm volatile("ldmatrix.sync.aligned.m8n8.x4.trans.shared.b16 {%0,%1,%2,%3}, [%4];"
                 : "=r"(r0), "=r"(r1), "=r"(r2), "=r"(r3) : "r"(addr));
}
// bf16 mma
__device__ __forceinline__ void mma16816(float* c, const uint32_t* a,
                                         uint32_t b0, uint32_t b1) {
    asm volatile(
        "mma.sync.aligned.m16n8k16.row.col.f32.bf16.bf16.f32 "
        "{%0,%1,%2,%3}, {%4,%5,%6,%7}, {%8,%9}, {%0,%1,%2,%3};"
        : "+f"(c[0]), "+f"(c[1]), "+f"(c[2]), "+f"(c[3])
        : "r"(a[0]), "r"(a[1]), "r"(a[2]), "r"(a[3]), "r"(b0), "r"(b1));
}
// fp16 mma
__device__ __forceinline__ void mma16816h(float* c, const uint32_t* a,
                                          uint32_t b0, uint32_t b1) {
    asm volatile(
        "mma.sync.aligned.m16n8k16.row.col.f32.f16.f16.f32 "
        "{%0,%1,%2,%3}, {%4,%5,%6,%7}, {%8,%9}, {%0,%1,%2,%3};"
        : "+f"(c[0]), "+f"(c[1]), "+f"(c[2]), "+f"(c[3])
        : "r"(a[0]), "r"(a[1]), "r"(a[2]), "r"(a[3]), "r"(b0), "r"(b1));
}

// ---------------------------------------------------------------------------
// hi/lo bf16 split
// ---------------------------------------------------------------------------
__device__ __forceinline__ void split_bf16(float v, __nv_bfloat16& h, __nv_bfloat16& l) {
    h = __float2bfloat16(v);
    l = __float2bfloat16(v - __bfloat162float(h));
}
__device__ __forceinline__ uint32_t pack_h2(float lo, float hi) {
    __half2 t = __floats2half2_rn(lo, hi);   // lo in low 16 bits
    return *(uint32_t*)&t;
}

// ---------------------------------------------------------------------------
// RMSNorm -> hi/lo bf16 split. One block (256 threads) per row.
// ---------------------------------------------------------------------------
__global__ __launch_bounds__(256)
void rmsnorm_split(const float* __restrict__ in, const float* __restrict__ w,
                   __nv_bfloat16* __restrict__ ohi, __nv_bfloat16* __restrict__ olo,
                   int ncols) {
    int row = blockIdx.x;
    const float* p = in + (size_t)row * ncols;
    size_t ob = (size_t)row * ncols;
    float ss = 0.f;
    for (int c = threadIdx.x; c < ncols; c += 256) { float v = p[c]; ss = fmaf(v, v, ss); }
    #pragma unroll
    for (int off = 16; off; off >>= 1) ss += __shfl_xor_sync(0xffffffffu, ss, off);
    __shared__ float red[8];
    int wid = threadIdx.x >> 5, lane = threadIdx.x & 31;
    if (lane == 0) red[wid] = ss;
    __syncthreads();
    float tot = 0.f;
    #pragma unroll
    for (int i = 0; i < 8; i++) tot += red[i];
    float r = rsqrtf(tot / (float)ncols + EPSF);
    for (int c = threadIdx.x; c < ncols; c += 256) {
        float v = p[c] * r * w[c];
        __nv_bfloat16 h, l; split_bf16(v, h, l);
        ohi[ob + c] = h; olo[ob + c] = l;
    }
}

// ---------------------------------------------------------------------------
// Weight transpose + split: W [K,N] fp32 -> Thi/Tlo [N,K] bf16
// ---------------------------------------------------------------------------
__global__ __launch_bounds__(256)
void wsplit(const float* __restrict__ W, __nv_bfloat16* __restrict__ Thi,
            __nv_bfloat16* __restrict__ Tlo, int K, int N) {
    __shared__ float t[32][33];
    int n0 = blockIdx.x * 32, k0 = blockIdx.y * 32;
    int tx = threadIdx.x & 31, ty = threadIdx.x >> 5;
    #pragma unroll
    for (int i = 0; i < 4; i++) {
        int k = ty + i * 8;
        t[k][tx] = W[(size_t)(k0 + k) * N + n0 + tx];
    }
    __syncthreads();
    #pragma unroll
    for (int i = 0; i < 4; i++) {
        int n = ty + i * 8;
        float v = t[tx][n];
        __nv_bfloat16 h, l; split_bf16(v, h, l);
        Thi[(size_t)(n0 + n) * K + k0 + tx] = h;
        Tlo[(size_t)(n0 + n) * K + k0 + tx] = l;
    }
}

// ---------------------------------------------------------------------------
// mma.sync bf16 GEMM, 3-term hi/lo split. 128x128 tile, BK=32, 8 warps.
// R6: 2 CTAs/SM (__launch_bounds__(256,2)); B fragments loaded on demand
// inside ni-loop to keep live registers <= 128.
// ---------------------------------------------------------------------------
#define APAD 40
#define TILE_B (128 * APAD * 2)
#define STAGE_B (4 * TILE_B)

__device__ __forceinline__ void gemm_load_stage(
    uint32_t st, const char* Ah, const char* Al, const char* Bh, const char* Bl,
    size_t rowb, size_t ko, int tid) {
    #pragma unroll
    for (int i = 0; i < 2; i++) {
        int idx = tid + i * 256;
        int r = idx >> 2, c = idx & 3;
        uint32_t dst = st + (uint32_t)(r * 80 + c * 16);
        size_t src = (size_t)r * rowb + ko + (size_t)c * 16;
        cp16(dst + 0u * TILE_B, Ah + src);
        cp16(dst + 1u * TILE_B, Al + src);
        cp16(dst + 2u * TILE_B, Bh + src);
        cp16(dst + 3u * TILE_B, Bl + src);
    }
    asm volatile("cp.async.commit_group;" ::: "memory");
}

template <int MODE>
__global__ __launch_bounds__(256, 2)
void gemm_mma(const __nv_bfloat16* __restrict__ Ahi, const __nv_bfloat16* __restrict__ Alo,
              const __nv_bfloat16* __restrict__ Bhi, const __nv_bfloat16* __restrict__ Blo,
              const float* __restrict__ Res, float* __restrict__ Cf,
              __nv_bfloat16* __restrict__ Chi, __nv_bfloat16* __restrict__ Clo,
              int M, int N, int K) {
    extern __shared__ char smem[];
    const uint32_t sb = smem_u32(smem);
    const int tid  = threadIdx.x;
    const int warp = tid >> 5, lane = tid & 31;
    const int warp_m = warp & 3;
    const int warp_n = warp >> 2;
    const int bm = blockIdx.y << 7;
    const int bn = blockIdx.x << 7;

    float acc[2][8][4];
    #pragma unroll
    for (int i = 0; i < 2; i++)
        #pragma unroll
        for (int j = 0; j < 8; j++)
            #pragma unroll
            for (int q = 0; q < 4; q++) acc[i][j][q] = 0.f;

    const size_t rowb = (size_t)K * 2;
    const char* Ah0 = (const char*)Ahi + (size_t)bm * rowb;
    const char* Al0 = (const char*)Alo + (size_t)bm * rowb;
    const char* Bh0 = (const char*)Bhi + (size_t)bn * rowb;
    const char* Bl0 = (const char*)Blo + (size_t)bn * rowb;

    const int NIT = K >> 5;

    gemm_load_stage(sb, Ah0, Al0, Bh0, Bl0, rowb, 0, tid);

    const int arow = warp_m * 32 + (lane & 15);
    const int acolb = ((lane >> 4) << 3);
    const int brow = warp_n * 64 + (lane & 7) + ((lane >> 4) << 3);
    const int bcolb = (lane & 8);

    for (int it = 0; it < NIT; it++) {
        if (it + 1 < NIT)
            gemm_load_stage(sb + (uint32_t)(((it + 1) & 1) * STAGE_B),
                            Ah0, Al0, Bh0, Bl0, rowb, (size_t)(it + 1) * 64, tid);
        if (it + 1 < NIT)
            asm volatile("cp.async.wait_group 1;" ::: "memory");
        else
            asm volatile("cp.async.wait_group 0;" ::: "memory");
        __syncthreads();

        const uint32_t st  = sb + (uint32_t)((it & 1) * STAGE_B);
        const uint32_t sah = st;
        const uint32_t sal = st + TILE_B;
        const uint32_t sbh = st + 2u * TILE_B;
        const uint32_t sbl = st + 3u * TILE_B;

        #pragma unroll
        for (int ks = 0; ks < 2; ks++) {
            uint32_t ah[2][4], al[2][4];
            const int acol = ks * 16 + acolb;
            const int bcol = ks * 16 + bcolb;
            #pragma unroll
            for (int mi = 0; mi < 2; mi++) {
                uint32_t off = (uint32_t)(((arow + mi * 16) * APAD + acol) * 2);
                ldsm_x4(ah[mi][0], ah[mi][1], ah[mi][2], ah[mi][3], sah + off);
                ldsm_x4(al[mi][0], al[mi][1], al[mi][2], al[mi][3], sal + off);
            }
            #pragma unroll
            for (int ni = 0; ni < 4; ni++) {
                uint32_t off = (uint32_t)(((brow + ni * 16) * APAD + bcol) * 2);
                uint32_t bh0, bh1, bh2, bh3, bl0, bl1, bl2, bl3;
                ldsm_x4(bh0, bh1, bh2, bh3, sbh + off);
                ldsm_x4(bl0, bl1, bl2, bl3, sbl + off);
                #pragma unroll
                for (int mi = 0; mi < 2; mi++) {
                    mma16816(acc[mi][2 * ni],     ah[mi], bh0, bh1);
                    mma16816(acc[mi][2 * ni + 1], ah[mi], bh2, bh3);
                    mma16816(acc[mi][2 * ni],     ah[mi], bl0, bl1);
                    mma16816(acc[mi][2 * ni + 1], ah[mi], bl2, bl3);
                    mma16816(acc[mi][2 * ni],     al[mi], bh0, bh1);
                    mma16816(acc[mi][2 * ni + 1], al[mi], bh2, bh3);
                }
            }
        }
        __syncthreads();
    }

    const int r0 = bm + warp_m * 32 + (lane >> 2);
    const int c0 = bn + warp_n * 64 + 2 * (lane & 3);
    #pragma unroll
    for (int mi = 0; mi < 2; mi++) {
        #pragma unroll
        for (int half = 0; half < 2; half++) {
            int row = r0 + mi * 16 + half * 8;
            size_t rb = (size_t)row * N;
            #pragma unroll
            for (int nj = 0; nj < 8; nj++) {
                int col = c0 + nj * 8;
                float v0 = acc[mi][nj][2 * half];
                float v1 = acc[mi][nj][2 * half + 1];
                size_t o = rb + col;
                if (MODE == 0) {
                    *(float2*)&Cf[o] = make_float2(v0, v1);
                } else if (MODE == 1) {
                    float2 rv = *(const float2*)&Res[o];
                    *(float2*)&Cf[o] = make_float2(v0 + rv.x, v1 + rv.y);
                } else {
                    float t0 = fmaxf(v0, 0.f); v0 = t0 * t0;
                    float t1 = fmaxf(v1, 0.f); v1 = t1 * t1;
                    __nv_bfloat16 h0, l0, h1, l1;
                    split_bf16(v0, h0, l0); split_bf16(v1, h1, l1);
                    *(__nv_bfloat162*)&Chi[o] = __nv_bfloat162(h0, h1);
                    *(__nv_bfloat162*)&Clo[o] = __nv_bfloat162(l0, l1);
                }
            }
        }
    }
}

// ---------------------------------------------------------------------------
// MXFP8 qdq (32-element block == one warp)
// ---------------------------------------------------------------------------
__device__ __forceinline__ float qdq32(float x) {
    float a = fabsf(x);
    #pragma unroll
    for (int off = 16; off; off >>= 1) a = fmaxf(a, __shfl_xor_sync(0xffffffffu, a, off));
    a = fmaxf(a, 1e-12f);
    int se = ilogbf(a) + 119;
    se = max(0, min(255, se));
    float scale = exp2f((float)(127 - se));
    float xs = fminf(fmaxf(x * scale, -448.f), 448.f);
    float xq = (float)__nv_fp8_e4m3(xs);
    return xq * exp2f((float)(se - 127));
}

// ---------------------------------------------------------------------------
// QKV post-process: RoPE -> head rmsnorm -> qdq -> (b,h,t,d) fp16 (exact)
// ---------------------------------------------------------------------------
__global__ __launch_bounds__(128)
void qkv_post(const float* __restrict__ qkv, const float* __restrict__ rope,
              const float* __restrict__ qn_w, const float* __restrict__ kn_w,
              __half* __restrict__ gq, __half* __restrict__ gk,
              __half* __restrict__ gv) {
    int idx = blockIdx.x;
    int h  = idx % NH;
    int bt = idx / NH;
    int t  = bt % NT;
    int b  = bt / NT;
    int d  = threadIdx.x;

    const float* base = qkv + (size_t)bt * NC3 + h * ND;
    float qv = base[d];
    float kv = base[NC + d];
    float vv = base[2 * NC + d];

    float fr = rope[t * ND + d];
    float sn, cs;
    sincosf(fr, &sn, &cs);
    __shared__ float sq[ND], sk[ND];
    sq[d] = qv; sk[d] = kv;
    __syncthreads();
    float qr = (d < 64) ? -sq[d + 64] : sq[d - 64];
    float kr = (d < 64) ? -sk[d + 64] : sk[d - 64];
    qv = qv * cs + qr * sn;
    kv = kv * cs + kr * sn;

    float s1 = qv * qv, s2 = kv * kv;
    #pragma unroll
    for (int off = 16; off; off >>= 1) {
        s1 += __shfl_xor_sync(0xffffffffu, s1, off);
        s2 += __shfl_xor_sync(0xffffffffu, s2, off);
    }
    __shared__ float r1[4], r2[4];
    int w = d >> 5, lane = d & 31;
    if (lane == 0) { r1[w] = s1; r2[w] = s2; }
    __syncthreads();
    float ssq = r1[0] + r1[1] + r1[2] + r1[3];
    float ssk = r2[0] + r2[1] + r2[2] + r2[3];
    qv *= rsqrtf(ssq * (1.f / ND) + EPSF) * qn_w[d];
    kv *= rsqrtf(ssk * (1.f / ND) + EPSF) * kn_w[d];

    qv = qdq32(qv);
    kv = qdq32(kv);
    vv = qdq32(vv);

    size_t o = (((size_t)(b * NH + h)) * NT + t) * ND + d;
    gq[o] = __float2half_rn(qv);   // exact: qdq values have <=4 mantissa bits
    gk[o] = __float2half_rn(kv);
    gv[o] = __float2half_rn(vv);
}

// ---------------------------------------------------------------------------
// Tensor-core causal flash attention (fp16 mma.sync).
// CTA: 128 q-rows, 8 warps x 16 rows. k-tiles of 64, D=128.
// S = Q K^T exact (qdq values exact in fp16); P single fp16 for P@V.
// ---------------------------------------------------------------------------
#define DP 136                        // padded row length (fp16 elems)
#define ATT_Q_ELEMS (128 * DP)
#define ATT_T_ELEMS (64 * DP)
#define ATT_SMEM2 ((ATT_Q_ELEMS + 4 * ATT_T_ELEMS) * 2)   // 104448 bytes

__device__ __forceinline__ void att_load_kv(uint32_t sK, uint32_t sV,
                                            const __half* Kg, const __half* Vg,
                                            int kb, int tid) {
    #pragma unroll
    for (int i = 0; i < 4; i++) {
        int idx = tid + i * 256;
        int r = idx >> 4, c = (idx & 15) << 3;
        uint32_t d = (uint32_t)((r * DP + c) * 2);
        cp16(sK + d, Kg + (size_t)(kb + r) * ND + c);
        cp16(sV + d, Vg + (size_t)(kb + r) * ND + c);
    }
    asm volatile("cp.async.commit_group;" ::: "memory");
}

__global__ __launch_bounds__(256)
void attn_mma(const __half* __restrict__ gq, const __half* __restrict__ gk,
              const __half* __restrict__ gv,
              __nv_bfloat16* __restrict__ ahi, __nv_bfloat16* __restrict__ alo) {
    extern __shared__ char sm2[];
    const uint32_t sQ = smem_u32(sm2);
    const uint32_t sKV = sQ + ATT_Q_ELEMS * 2;

    const int tid  = threadIdx.x;
    const int warp = tid >> 5, lane = tid & 31;
    const int g  = lane >> 2, qr = lane & 3;
    const int qblk = blockIdx.x;
    const int q0   = qblk << 7;
    const int bh   = blockIdx.y;
    const int b    = bh / NH, h = bh % NH;

    const __half* Qg = gq + ((size_t)bh * NT + q0) * ND;
    const __half* Kg = gk + (size_t)bh * NT * ND;
    const __half* Vg = gv + (size_t)bh * NT * ND;

    // stage Q (128x128) into smem
    #pragma unroll
    for (int i = 0; i < 8; i++) {
        int idx = tid + i * 256;
        int r = idx >> 4, c = (idx & 15) << 3;
        cp16(sQ + (uint32_t)((r * DP + c) * 2), Qg + (size_t)r * ND + c);
    }
    asm volatile("cp.async.commit_group;" ::: "memory");
    att_load_kv(sKV, sKV + ATT_T_ELEMS * 2, Kg, Vg, 0, tid);
    asm volatile("cp.async.wait_group 0;" ::: "memory");
    __syncthreads();

    // Q fragments (register resident)
    uint32_t qa[8][4];
    {
        const uint32_t qbase = sQ + (uint32_t)(((warp * 16 + (lane & 15)) * DP
                                                + ((lane >> 4) << 3)) * 2);
        #pragma unroll
        for (int ks = 0; ks < 8; ks++)
            ldsm_x4(qa[ks][0], qa[ks][1], qa[ks][2], qa[ks][3], qbase + ks * 32);
    }

    float oc[16][4];
    #pragma unroll
    for (int i = 0; i < 16; i++)
        #pragma unroll
        for (int j = 0; j < 4; j++) oc[i][j] = 0.f;
    float m0 = -INFINITY, m1 = -INFINITY, l0 = 0.f, l1 = 0.f;
    const int row0 = q0 + warp * 16 + g;
    const int row1 = row0 + 8;
    const int wrow_max = q0 + warp * 16 + 15;

    const int nkt = 2 * qblk + 2;
    for (int kt = 0; kt < nkt; kt++) {
        if (kt + 1 < nkt)
            att_load_kv(sKV + (uint32_t)(((kt + 1) & 1) * 2 * ATT_T_ELEMS * 2),
                        sKV + (uint32_t)((((kt + 1) & 1) * 2 + 1) * ATT_T_ELEMS * 2),
                        Kg, Vg, (kt + 1) << 6, tid);

        const int kb = kt << 6;
        if (kb <= wrow_max) {
            const uint32_t sK = sKV + (uint32_t)((kt & 1) * 2 * ATT_T_ELEMS * 2);
            const uint32_t sV = sK + (uint32_t)(ATT_T_ELEMS * 2);

            // S = Q K^T (8 n-tiles x 8 k-steps)
            float s[8][4];
            #pragma unroll
            for (int j = 0; j < 8; j++)
                #pragma unroll
                for (int q = 0; q < 4; q++) s[j][q] = 0.f;
            #pragma unroll
            for (int np = 0; np < 4; np++) {
                const uint32_t ka = sK + (uint32_t)(((np * 16 + (lane & 7)
                                  + ((lane >> 4) << 3)) * DP + (((lane >> 3) & 1) << 3)) * 2);
                #pragma unroll
                for (int ks = 0; ks < 8; ks++) {
                    uint32_t b0, b1, b2, b3;
                    ldsm_x4(b0, b1, b2, b3, ka + ks * 32);
                    mma16816h(s[2 * np],     qa[ks], b0, b1);
                    mma16816h(s[2 * np + 1], qa[ks], b2, b3);
                }
            }

            // scale + causal mask + row max
            float mx0 = -INFINITY, mx1 = -INFINITY;
            #pragma unroll
            for (int j = 0; j < 8; j++) {
                int c0 = kb + j * 8 + qr * 2;
                s[j][0] = (c0     <= row0) ? s[j][0] * ATT_SCALE : -INFINITY;
                s[j][1] = (c0 + 1 <= row0) ? s[j][1] * ATT_SCALE : -INFINITY;
                s[j][2] = (c0     <= row1) ? s[j][2] * ATT_SCALE : -INFINITY;
                s[j][3] = (c0 + 1 <= row1) ? s[j][3] * ATT_SCALE : -INFINITY;
                mx0 = fmaxf(mx0, fmaxf(s[j][0], s[j][1]));
                mx1 = fmaxf(mx1, fmaxf(s[j][2], s[j][3]));
            }
            mx0 = fmaxf(mx0, __shfl_xor_sync(0xffffffffu, mx0, 1));
            mx0 = fmaxf(mx0, __shfl_xor_sync(0xffffffffu, mx0, 2));
            mx1 = fmaxf(mx1, __shfl_xor_sync(0xffffffffu, mx1, 1));
            mx1 = fmaxf(mx1, __shfl_xor_sync(0xffffffffu, mx1, 2));

            float mn0 = fmaxf(m0, mx0), mn1 = fmaxf(m1, mx1);
            float al0 = __expf(m0 - mn0), al1 = __expf(m1 - mn1);
            m0 = mn0; m1 = mn1;

            // exp -> P (single fp16 fragments)
            uint32_t ph[8][2];
            float ls0 = 0.f, ls1 = 0.f;
            #pragma unroll
            for (int j = 0; j < 8; j++) {
                float p0 = __expf(s[j][0] - mn0);
                float p1 = __expf(s[j][1] - mn0);
                float p2 = __expf(s[j][2] - mn1);
                float p3 = __expf(s[j][3] - mn1);
                ls0 += p0 + p1; ls1 += p2 + p3;
                ph[j][0] = pack_h2(p0, p1);
                ph[j][1] = pack_h2(p2, p3);
            }
            l0 = l0 * al0 + ls0;
            l1 = l1 * al1 + ls1;

            // rescale O
            #pragma unroll
            for (int nt = 0; nt < 16; nt++) {
                oc[nt][0] *= al0; oc[nt][1] *= al0;
                oc[nt][2] *= al1; oc[nt][3] *= al1;
            }

            // O += P V  (4 k-steps x 8 n-pairs)
            #pragma unroll
            for (int ks = 0; ks < 4; ks++) {
                uint32_t pa[4] = { ph[2*ks][0], ph[2*ks][1], ph[2*ks+1][0], ph[2*ks+1][1] };
                const uint32_t va0 = sV + (uint32_t)(((ks * 16 + (lane & 7)
                                   + ((lane >> 3) & 1) * 8) * DP + ((lane >> 4) << 3)) * 2);
                #pragma unroll
                for (int np = 0; np < 8; np++) {
                    uint32_t b0, b1, b2, b3;
                    ldsm_x4t(b0, b1, b2, b3, va0 + np * 32);
                    mma16816h(oc[2 * np],     pa, b0, b1);
                    mma16816h(oc[2 * np + 1], pa, b2, b3);
                }
            }
        }

        if (kt + 1 < nkt)
            asm volatile("cp.async.wait_group 0;" ::: "memory");
        __syncthreads();
    }

    // quad-reduce the per-lane partial row sums (m was quad-uniform)
    l0 += __shfl_xor_sync(0xffffffffu, l0, 1);
    l0 += __shfl_xor_sync(0xffffffffu, l0, 2);
    l1 += __shfl_xor_sync(0xffffffffu, l1, 1);
    l1 += __shfl_xor_sync(0xffffffffu, l1, 2);

    // epilogue: normalize, hi/lo split, write (b, t, h*128 + d)
    const float li0 = 1.f / l0, li1 = 1.f / l1;
    const size_t ob0 = ((size_t)b * NT + row0) * NC + h * ND;
    const size_t ob1 = ((size_t)b * NT + row1) * NC + h * ND;
    #pragma unroll
    for (int nt = 0; nt < 16; nt++) {
        int col = nt * 8 + qr * 2;
        float v0 = oc[nt][0] * li0, v1 = oc[nt][1] * li0;
        float v2 = oc[nt][2] * li1, v3 = oc[nt][3] * li1;
        __nv_bfloat16 h0, lw0, h1, lw1, h2, lw2, h3, lw3;
        split_bf16(v0, h0, lw0); split_bf16(v1, h1, lw1);
        split_bf16(v2, h2, lw2); split_bf16(v3, h3, lw3);
        *(__nv_bfloat162*)&ahi[ob0 + col] = __nv_bfloat162(h0, h1);
        *(__nv_bfloat162*)&alo[ob0 + col] = __nv_bfloat162(lw0, lw1);
        *(__nv_bfloat162*)&ahi[ob1 + col] = __nv_bfloat162(h2, h3);
        *(__nv_bfloat162*)&alo[ob1 + col] = __nv_bfloat162(lw2, lw3);
    }
}

// ---------------------------------------------------------------------------
// Launch
// ---------------------------------------------------------------------------
static const int GEMM_SMEM = 2 * STAGE_B;

extern "C" void kernel_launch(void* const* d_in, const int* in_sizes, int n_in,
                              void* d_out, int out_size) {
    const float* x      = (const float*)d_in[0];
    const float* rope   = (const float*)d_in[1];
    const float* ln1_w  = (const float*)d_in[2];
    const float* w_qkv  = (const float*)d_in[3];
    const float* qn_w   = (const float*)d_in[4];
    const float* kn_w   = (const float*)d_in[5];
    const float* w_out  = (const float*)d_in[6];
    const float* ln2_w  = (const float*)d_in[7];
    const float* w_fc1  = (const float*)d_in[8];
    const float* w_fc2  = (const float*)d_in[9];
    float* out = (float*)d_out;

    float *qkv, *y1;
    __half *qb, *kb, *vb;
    __nv_bfloat16 *xnh, *xnl, *ath, *atl, *hh, *hl;
    __nv_bfloat16 *wqh, *wql, *woh, *wol, *w1h, *w1l, *w2h, *w2l;
    cudaGetSymbolAddress((void**)&xnh, g_xn_hi);
    cudaGetSymbolAddress((void**)&xnl, g_xn_lo);
    cudaGetSymbolAddress((void**)&qkv, g_qkv);
    cudaGetSymbolAddress((void**)&qb,  g_qb);
    cudaGetSymbolAddress((void**)&kb,  g_kb);
    cudaGetSymbolAddress((void**)&vb,  g_vb);
    cudaGetSymbolAddress((void**)&ath, g_at_hi);
    cudaGetSymbolAddress((void**)&atl, g_at_lo);
    cudaGetSymbolAddress((void**)&y1,  g_y1);
    cudaGetSymbolAddress((void**)&hh,  g_h_hi);
    cudaGetSymbolAddress((void**)&hl,  g_h_lo);
    cudaGetSymbolAddress((void**)&wqh, g_wqkvT_h);
    cudaGetSymbolAddress((void**)&wql, g_wqkvT_l);
    cudaGetSymbolAddress((void**)&woh, g_woutT_h);
    cudaGetSymbolAddress((void**)&wol, g_woutT_l);
    cudaGetSymbolAddress((void**)&w1h, g_wfc1T_h);
    cudaGetSymbolAddress((void**)&w1l, g_wfc1T_l);
    cudaGetSymbolAddress((void**)&w2h, g_wfc2T_h);
    cudaGetSymbolAddress((void**)&w2l, g_wfc2T_l);

    cudaFuncSetAttribute(attn_mma, cudaFuncAttributeMaxDynamicSharedMemorySize, ATT_SMEM2);
    cudaFuncSetAttribute(gemm_mma<0>, cudaFuncAttributeMaxDynamicSharedMemorySize, GEMM_SMEM);
    cudaFuncSetAttribute(gemm_mma<1>, cudaFuncAttributeMaxDynamicSharedMemorySize, GEMM_SMEM);
    cudaFuncSetAttribute(gemm_mma<2>, cudaFuncAttributeMaxDynamicSharedMemorySize, GEMM_SMEM);

    // Weight transpose+split
    wsplit<<<dim3(NC3 / 32, NC / 32), 256>>>(w_qkv, wqh, wql, NC, NC3);
    wsplit<<<dim3(NC  / 32, NC / 32), 256>>>(w_out, woh, wol, NC, NC);
    wsplit<<<dim3(NF  / 32, NC / 32), 256>>>(w_fc1, w1h, w1l, NC, NF);
    wsplit<<<dim3(NC  / 32, NF / 32), 256>>>(w_fc2, w2h, w2l, NF, NC);

    // 1) rmsnorm(x) -> hi/lo
    rmsnorm_split<<<NBT, 256>>>(x, ln1_w, xnh, xnl, NC);

    // 2) qkv = xn @ w_qkv (fp32 out)
    gemm_mma<0><<<dim3(NC3 / 128, NBT / 128), 256, GEMM_SMEM>>>(
        xnh, xnl, wqh, wql, nullptr, qkv, nullptr, nullptr, NBT, NC3, NC);

    // 3) RoPE + head rmsnorm + mxfp8 qdq -> fp16 (exact)
    qkv_post<<<NB * NT * NH, 128>>>(qkv, rope, qn_w, kn_w, qb, kb, vb);

    // 4) tensor-core causal attention -> hi/lo
    attn_mma<<<dim3(NT / 128, NB * NH), 256, ATT_SMEM2>>>(qb, kb, vb, ath, atl);

    // 5) y1 = x + attn @ w_out
    gemm_mma<1><<<dim3(NC / 128, NBT / 128), 256, GEMM_SMEM>>>(
        ath, atl, woh, wol, x, y1, nullptr, nullptr, NBT, NC, NC);

    // 6) rmsnorm(y1) -> hi/lo
    rmsnorm_split<<<NBT, 256>>>(y1, ln2_w, xnh, xnl, NC);

    // 7) h = srelu(xn @ w_fc1) -> hi/lo
    gemm_mma<2><<<dim3(NF / 128, NBT / 128), 256, GEMM_SMEM>>>(
        xnh, xnl, w1h, w1l, nullptr, nullptr, hh, hl, NBT, NF, NC);

    // 8) out = y1 + h @ w_fc2
    gemm_mma<1><<<dim3(NC / 128, NBT / 128), 256, GEMM_SMEM>>>(
        hh, hl, w2h, w2l, y1, out, nullptr, nullptr, NBT, NC, NF);
}